// round 10
// baseline (speedup 1.0000x reference)
#include <cuda_runtime.h>
#include <cuda_bf16.h>
#include <cuda_fp16.h>
#include <cstdint>

// Problem dims (fixed by the dataset)
#define BB     8
#define FF     8192
#define NLAT   64
#define DD     1024
#define HH     8
#define DHD    64
#define INNER  512
#define KVLEN  (FF + NLAT)          // 8256
#define MROWS  (BB * KVLEN)         // 66048
#define NSPLIT 16
#define JT     32                    // kv tile in attention
#define NTILES (KVLEN / JT)          // 258
#define TPS    ((NTILES + NSPLIT - 1) / NSPLIT)  // 17
#define LN_EPS 1e-5f

// ---------------- family-safe PTX helpers (sm_80-era; no 'a'-features) ------
__device__ __forceinline__ uint32_t smem_u32(const void* p) {
    uint32_t a;
    asm("{ .reg .u64 t; cvta.to.shared.u64 t, %1; cvt.u32.u64 %0, t; }" : "=r"(a) : "l"(p));
    return a;
}
__device__ __forceinline__ void cp_async16(uint32_t dst, const void* src) {
    asm volatile("cp.async.cg.shared.global [%0], [%1], 16;" :: "r"(dst), "l"(src));
}
#define CP_COMMIT() asm volatile("cp.async.commit_group;" ::: "memory")
#define CP_WAIT(n)  asm volatile("cp.async.wait_group %0;" :: "n"(n) : "memory")

__device__ __forceinline__ void ldsm_x4(uint32_t* r, uint32_t addr) {
    asm volatile("ldmatrix.sync.aligned.m8n8.x4.shared.b16 {%0,%1,%2,%3}, [%4];"
        : "=r"(r[0]), "=r"(r[1]), "=r"(r[2]), "=r"(r[3]) : "r"(addr));
}
__device__ __forceinline__ void ldsm_x4_trans(uint32_t* r, uint32_t addr) {
    asm volatile("ldmatrix.sync.aligned.m8n8.x4.trans.shared.b16 {%0,%1,%2,%3}, [%4];"
        : "=r"(r[0]), "=r"(r[1]), "=r"(r[2]), "=r"(r[3]) : "r"(addr));
}
// bf16 mma (attention path)
__device__ __forceinline__ void mma16816(float* c, const uint32_t* a,
                                         uint32_t b0, uint32_t b1) {
    asm volatile(
        "mma.sync.aligned.m16n8k16.row.col.f32.bf16.bf16.f32 "
        "{%0,%1,%2,%3}, {%4,%5,%6,%7}, {%8,%9}, {%0,%1,%2,%3};"
        : "+f"(c[0]), "+f"(c[1]), "+f"(c[2]), "+f"(c[3])
        : "r"(a[0]), "r"(a[1]), "r"(a[2]), "r"(a[3]), "r"(b0), "r"(b1));
}
// fp16 mma (kv projection path)
__device__ __forceinline__ void mma16816h(float* c, const uint32_t* a,
                                          uint32_t b0, uint32_t b1) {
    asm volatile(
        "mma.sync.aligned.m16n8k16.row.col.f32.f16.f16.f32 "
        "{%0,%1,%2,%3}, {%4,%5,%6,%7}, {%8,%9}, {%0,%1,%2,%3};"
        : "+f"(c[0]), "+f"(c[1]), "+f"(c[2]), "+f"(c[3])
        : "r"(a[0]), "r"(a[1]), "r"(a[2]), "r"(a[3]), "r"(b0), "r"(b1));
}

// -------- scratch (device globals; no allocations allowed) --------
__device__ float          g_lat_ln[BB * NLAT * DD];                       // 2 MB
__device__ __half         g_af[(size_t)MROWS * DD];                       // 135 MB (A fp16)
__device__ __half         g_bf[1024 * 1024];                              // 2 MB  [n][k] fp16
__device__ __nv_bfloat16  g_kvhi[(size_t)MROWS * 1024];                   // 135 MB (cols 0-511 K, 512-1023 V)
__device__ __nv_bfloat16  g_kvlo[(size_t)MROWS * 1024];                   // 135 MB
__device__ float          g_qmat[BB * NLAT * INNER];                      // 1 MB
__device__ float          g_attnout[BB * NLAT * INNER];                   // 1 MB
__device__ float          g_pacc[(size_t)BB * HH * NSPLIT * NLAT * DHD];  // 16.8 MB
__device__ float          g_pm[BB * HH * NSPLIT * NLAT];
__device__ float          g_pl[BB * HH * NSPLIT * NLAT];
__device__ int            g_mask_is_byte;

// ---- LayerNorm of latents + (block 0) mask dtype detection ----
__global__ __launch_bounds__(256) void ln_lat_kernel(const float* __restrict__ lat,
                                                     const float* __restrict__ gamma,
                                                     const float* __restrict__ beta,
                                                     const unsigned int* __restrict__ mask_w) {
    int row = blockIdx.x;
    int t = threadIdx.x;
    if (row == 0 && t == 0) {
        unsigned int acc = 0;
        #pragma unroll
        for (int i = 0; i < 64; i++) acc |= mask_w[i];
        g_mask_is_byte = (acc > 1u) ? 1 : 0;
    }
    float4 v = ((const float4*)(lat + (size_t)row * DD))[t];
    __shared__ float rs[256], rq[256];
    rs[t] = v.x + v.y + v.z + v.w;
    rq[t] = v.x*v.x + v.y*v.y + v.z*v.z + v.w*v.w;
    __syncthreads();
    for (int off = 128; off > 0; off >>= 1) {
        if (t < off) { rs[t] += rs[t + off]; rq[t] += rq[t + off]; }
        __syncthreads();
    }
    float mu   = rs[0] * (1.f / DD);
    float var  = rq[0] * (1.f / DD) - mu * mu;
    float rstd = rsqrtf(var + LN_EPS);
    float4 gv = ((const float4*)gamma)[t];
    float4 bv = ((const float4*)beta)[t];
    float4 o;
    o.x = (v.x - mu) * rstd * gv.x + bv.x;
    o.y = (v.y - mu) * rstd * gv.y + bv.y;
    o.z = (v.z - mu) * rstd * gv.z + bv.z;
    o.w = (v.w - mu) * rstd * gv.w + bv.w;
    ((float4*)(g_lat_ln + (size_t)row * DD))[t] = o;
}

// ---- fused LN + fp16 store of the KV input matrix A ----
__global__ __launch_bounds__(256) void prep_a_kernel(const float* __restrict__ x,
                                                     const float* __restrict__ gm_,
                                                     const float* __restrict__ bm_,
                                                     const float* __restrict__ gate_p) {
    int row = blockIdx.x;                 // 0..MROWS-1
    int b = row / KVLEN;
    int r = row - b * KVLEN;
    int t = threadIdx.x;
    float4 y;
    if (r < FF) {
        float4 v = ((const float4*)(x + ((size_t)b * FF + r) * DD))[t];
        __shared__ float rs[256], rq[256];
        rs[t] = v.x + v.y + v.z + v.w;
        rq[t] = v.x*v.x + v.y*v.y + v.z*v.z + v.w*v.w;
        __syncthreads();
        for (int off = 128; off > 0; off >>= 1) {
            if (t < off) { rs[t] += rs[t + off]; rq[t] += rq[t + off]; }
            __syncthreads();
        }
        float mu   = rs[0] * (1.f / DD);
        float var  = rq[0] * (1.f / DD) - mu * mu;
        float rstd = rsqrtf(var + LN_EPS);
        float4 gv = ((const float4*)gm_)[t];
        float4 bv = ((const float4*)bm_)[t];
        y.x = (v.x - mu) * rstd * gv.x + bv.x;
        y.y = (v.y - mu) * rstd * gv.y + bv.y;
        y.z = (v.z - mu) * rstd * gv.z + bv.z;
        y.w = (v.w - mu) * rstd * gv.w + bv.w;
    } else {
        float4 v = ((const float4*)(g_lat_ln + ((size_t)b * NLAT + (r - FF)) * DD))[t];
        float gate = gate_p[0];
        y.x = v.x * gate; y.y = v.y * gate; y.z = v.z * gate; y.w = v.w * gate;
    }
    __half2* d = (__half2*)(g_af + (size_t)row * DD) + 2 * t;
    d[0] = __floats2half2_rn(y.x, y.y);
    d[1] = __floats2half2_rn(y.z, y.w);
}

// ---- transpose [Wk|Wv] (k-major [1024][512] each) into B[n][k] fp16 ----
__global__ __launch_bounds__(256) void prep_w_kernel(const float* __restrict__ Wk,
                                                     const float* __restrict__ Wv) {
    __shared__ float tile[32][33];
    int n0 = blockIdx.x * 32;           // 0..1023 (n of concat)
    int k0 = blockIdx.y * 32;
    int tx = threadIdx.x & 31, ty = threadIdx.x >> 5;  // 32 x 8
    const float* W = (n0 < 512) ? Wk : Wv;
    int nn0 = (n0 < 512) ? n0 : (n0 - 512);
    for (int i = ty; i < 32; i += 8)
        tile[i][tx] = W[(size_t)(k0 + i) * 512 + nn0 + tx];
    __syncthreads();
    for (int i = ty; i < 32; i += 8) {
        float v = tile[tx][i];          // = W[k0+tx][nn0+i]
        g_bf[(size_t)(n0 + i) * 1024 + k0 + tx] = __float2half_rn(v);
    }
}

// ---- HMMA (mma.sync fp16, 1-term) K/V projection: kv = A @ B^T ----
// BM=128, BN=128, BK=32. 128 thr = 4 warps (2m x 2n), warp tile 64x64.
// (R9 had 8 warps of 32x64: smem-read amplification 2.4x and only 32 HMMA
//  between barriers per warp; 64x64 cuts reads 33% and doubles per-warp ILP.)
// 4-stage cp.async pipeline, stage = {A, B} = 20480 B -> 2 CTAs/SM.
#define AS_STRIDE_H 40                      // halves per SMEM row
#define MAT_BYTES   (128 * AS_STRIDE_H * 2) // 10240 per matrix tile
#define STG_BYTES   (2 * MAT_BYTES)         // 20480 per stage (A, B)
#define NSTAGE      4
#define GEMM_SMEM   (NSTAGE * STG_BYTES)    // 81920
#define NCHUNK      32

__global__ __launch_bounds__(128, 2) void kv_mma_kernel() {
    extern __shared__ char smem[];
    const uint32_t sbase = smem_u32(smem);
    const int t = threadIdx.x;
    const int wid = t >> 5, lane = t & 31;
    const int ntile = blockIdx.x;            // 0..7
    const int mtile = blockIdx.y;            // 0..515
    const size_t arow0 = (size_t)mtile * 128;
    const int    brow0 = ntile * 128;

    // global load assignment: thread t owns full row t of A and B (4 segs each)
    const __half* gA = g_af + (arow0 + t) * 1024;
    const __half* gB = g_bf + (size_t)(brow0 + t) * 1024;
    const uint32_t sdst = sbase + t * 80;

    #define LOAD_CHUNK(chunk, stg_) do {                                       \
        uint32_t sb_ = sdst + (stg_) * STG_BYTES;                              \
        int ko_ = (chunk) * 32;                                                \
        cp_async16(sb_,                  gA + ko_);                            \
        cp_async16(sb_ + 16,             gA + ko_ + 8);                        \
        cp_async16(sb_ + 32,             gA + ko_ + 16);                       \
        cp_async16(sb_ + 48,             gA + ko_ + 24);                       \
        cp_async16(sb_ + MAT_BYTES,      gB + ko_);                            \
        cp_async16(sb_ + MAT_BYTES + 16, gB + ko_ + 8);                        \
        cp_async16(sb_ + MAT_BYTES + 32, gB + ko_ + 16);                       \
        cp_async16(sb_ + MAT_BYTES + 48, gB + ko_ + 24);                       \
    } while (0)

    // warp tile: wm in {0,64}, wn in {0,64}
    const int wm = (wid & 1) * 64;
    const int wn = (wid >> 1) * 64;

    const int a_off_h = (wm + (lane & 15)) * AS_STRIDE_H + (lane >> 4) * 8;
    const int b_off_h = (wn + (lane & 7) + ((lane >> 3) & 1) * 8) * AS_STRIDE_H
                        + (lane >> 4) * 8;

    float acc[4][8][4];
    #pragma unroll
    for (int i = 0; i < 4; i++)
        #pragma unroll
        for (int j = 0; j < 8; j++)
            #pragma unroll
            for (int c = 0; c < 4; c++) acc[i][j][c] = 0.f;

    LOAD_CHUNK(0, 0); CP_COMMIT();
    LOAD_CHUNK(1, 1); CP_COMMIT();
    LOAD_CHUNK(2, 2); CP_COMMIT();

    int st = 0;  // stage of current chunk
    for (int chunk = 0; chunk < NCHUNK; chunk++) {
        if (chunk < NCHUNK - 2)       { CP_WAIT(2); }
        else if (chunk == NCHUNK - 2) { CP_WAIT(1); }
        else                          { CP_WAIT(0); }
        __syncthreads();   // also protects WAR on the stage being refilled
        if (chunk + 3 < NCHUNK) {
            int stn = st + 3; if (stn >= NSTAGE) stn -= NSTAGE;
            LOAD_CHUNK(chunk + 3, stn);
            CP_COMMIT();
        }

        const uint32_t stg = sbase + st * STG_BYTES;
        #pragma unroll
        for (int ks = 0; ks < 2; ks++) {
            uint32_t a[4][4];
            #pragma unroll
            for (int mi = 0; mi < 4; mi++) {
                uint32_t ao = stg + (a_off_h + mi * 16 * AS_STRIDE_H + ks * 16) * 2;
                ldsm_x4(a[mi], ao);
            }
            #pragma unroll
            for (int nip = 0; nip < 4; nip++) {
                uint32_t bb[4];
                uint32_t bo = stg + MAT_BYTES
                            + (b_off_h + nip * 16 * AS_STRIDE_H + ks * 16) * 2;
                ldsm_x4(bb, bo);
                #pragma unroll
                for (int mi = 0; mi < 4; mi++) {
                    mma16816h(acc[mi][nip * 2],     a[mi], bb[0], bb[2]);
                    mma16816h(acc[mi][nip * 2 + 1], a[mi], bb[1], bb[3]);
                }
            }
        }
        if (++st == NSTAGE) st = 0;
    }

    // epilogue: split fp32 C to bf16 hi/lo, write g_kvhi / g_kvlo
    const int col0 = ntile * 128 + wn + (lane & 3) * 2;
    #pragma unroll
    for (int mi = 0; mi < 4; mi++) {
        size_t row = arow0 + wm + mi * 16 + (lane >> 2);
        #pragma unroll
        for (int ni = 0; ni < 8; ni++) {
            float v0 = acc[mi][ni][0], v1 = acc[mi][ni][1];
            float v2 = acc[mi][ni][2], v3 = acc[mi][ni][3];
            __nv_bfloat162 h01 = __floats2bfloat162_rn(v0, v1);
            __nv_bfloat162 h23 = __floats2bfloat162_rn(v2, v3);
            __nv_bfloat162 l01 = __floats2bfloat162_rn(v0 - __bfloat162float(h01.x),
                                                       v1 - __bfloat162float(h01.y));
            __nv_bfloat162 l23 = __floats2bfloat162_rn(v2 - __bfloat162float(h23.x),
                                                       v3 - __bfloat162float(h23.y));
            size_t o0 = row * 1024 + col0 + ni * 8;
            size_t o1 = (row + 8) * 1024 + col0 + ni * 8;
            *(__nv_bfloat162*)(g_kvhi + o0) = h01;
            *(__nv_bfloat162*)(g_kvlo + o0) = l01;
            *(__nv_bfloat162*)(g_kvhi + o1) = h23;
            *(__nv_bfloat162*)(g_kvlo + o1) = l23;
        }
    }
}

// ---- generic small sgemm (mode 0: Q proj, mode 1: out proj) ----
__global__ __launch_bounds__(256) void sgemm_kernel(const float* __restrict__ Bmat,
                                                    float* __restrict__ Cext,
                                                    int M, int N, int K,
                                                    int lda, int ldb, int ldc,
                                                    float alpha, int mode) {
    const float* A = (mode == 0) ? g_lat_ln : g_attnout;
    float* C = (mode == 0) ? g_qmat : Cext;
    __shared__ float As[16][65];
    __shared__ float Bs[16][65];
    int t = threadIdx.x;
    int tx = t & 15, ty = t >> 4;
    int n0 = blockIdx.x * 64;
    int m0 = blockIdx.y * 64;
    float acc[4][4] = {};
    for (int k0 = 0; k0 < K; k0 += 16) {
        #pragma unroll
        for (int l = 0; l < 4; l++) {
            int idx = t + l * 256;
            int row = idx >> 4, kk = idx & 15;
            As[kk][row] = A[(size_t)(m0 + row) * lda + k0 + kk];
        }
        #pragma unroll
        for (int l = 0; l < 4; l++) {
            int idx = t + l * 256;
            int kk = idx >> 6, col = idx & 63;
            Bs[kk][col] = Bmat[(size_t)(k0 + kk) * ldb + n0 + col];
        }
        __syncthreads();
        #pragma unroll
        for (int kk = 0; kk < 16; kk++) {
            float a[4], bb[4];
            #pragma unroll
            for (int i = 0; i < 4; i++) a[i]  = As[kk][ty * 4 + i];
            #pragma unroll
            for (int j = 0; j < 4; j++) bb[j] = Bs[kk][tx * 4 + j];
            #pragma unroll
            for (int i = 0; i < 4; i++)
                #pragma unroll
                for (int j = 0; j < 4; j++)
                    acc[i][j] = fmaf(a[i], bb[j], acc[i][j]);
        }
        __syncthreads();
    }
    #pragma unroll
    for (int i = 0; i < 4; i++)
        #pragma unroll
        for (int j = 0; j < 4; j++)
            C[(size_t)(m0 + ty * 4 + i) * ldc + n0 + tx * 4 + j] = alpha * acc[i][j];
}

// ---- split-KV flash attention with HMMA (bf16 3-term) ----
#define ATT_QSTR 72
#define ATT_KSTR 72
#define ATT_PSTR 40
#define ATT_SSTR 40
#define AOFF_QH 0
#define AOFF_QL 9216
#define AOFF_KH 18432
#define AOFF_KL 23040
#define AOFF_VH 27648
#define AOFF_VL 32256
#define AOFF_SP 36864
#define AOFF_PH 47104
#define AOFF_PL 52224
#define AOFF_M  57344
#define AOFF_L  57600
#define AOFF_AL 57856
#define AOFF_MN 58112
#define AOFF_VD 58368
#define ATT_SMEM 58496

__global__ __launch_bounds__(256) void attn_mma_kernel(const void* __restrict__ mask_raw) {
    extern __shared__ char sm[];
    const uint32_t sb = smem_u32(sm);
    const int split = blockIdx.x, h = blockIdx.y, b = blockIdx.z;
    const int t = threadIdx.x, wid = t >> 5, lane = t & 31;
    const unsigned char* mask8 = (const unsigned char*)mask_raw;
    const int*           mask32 = (const int*)mask_raw;
    const int is_byte = g_mask_is_byte;

    float* mf  = (float*)(sm + AOFF_M);
    float* lf  = (float*)(sm + AOFF_L);
    float* alf = (float*)(sm + AOFF_AL);
    float* mnf = (float*)(sm + AOFF_MN);
    float* vdf = (float*)(sm + AOFF_VD);

    // prologue: load+split Q slice (64q x 64d) to Qh/Ql
    {
        int q = t >> 2, dg = (t & 3) * 16;
        const float4* src = (const float4*)(g_qmat + ((size_t)(b * NLAT + q)) * INNER
                                            + h * DHD + dg);
        __nv_bfloat162* qh = (__nv_bfloat162*)(sm + AOFF_QH + (q * ATT_QSTR + dg) * 2);
        __nv_bfloat162* ql = (__nv_bfloat162*)(sm + AOFF_QL + (q * ATT_QSTR + dg) * 2);
        #pragma unroll
        for (int i = 0; i < 4; i++) {
            float4 v = src[i];
            __nv_bfloat162 h01 = __floats2bfloat162_rn(v.x, v.y);
            __nv_bfloat162 h23 = __floats2bfloat162_rn(v.z, v.w);
            __nv_bfloat162 l01 = __floats2bfloat162_rn(v.x - __bfloat162float(h01.x),
                                                       v.y - __bfloat162float(h01.y));
            __nv_bfloat162 l23 = __floats2bfloat162_rn(v.z - __bfloat162float(h23.x),
                                                       v.w - __bfloat162float(h23.y));
            qh[i * 2] = h01; qh[i * 2 + 1] = h23;
            ql[i * 2] = l01; ql[i * 2 + 1] = l23;
        }
    }
    if (t < 64) { mf[t] = -1e30f; lf[t] = 0.f; }

    float acc[4][4];
    #pragma unroll
    for (int i = 0; i < 4; i++)
        #pragma unroll
        for (int j = 0; j < 4; j++) acc[i][j] = 0.f;

    const int t0 = split * TPS;
    int tcnt = NTILES - t0;
    if (tcnt > TPS) tcnt = TPS;
    if (tcnt < 0) tcnt = 0;
    __syncthreads();

    for (int it = 0; it < tcnt; it++) {
        const int j0 = (t0 + it) * JT;
        // phase 1: K/V hi/lo tiles, full coverage: 32 rows x 8 segs, 1 seg/thread
        {
            int row = t >> 3;              // 0..31
            int seg = (t & 7) * 8;         // halves
            const __nv_bfloat16* shi = g_kvhi + ((size_t)b * KVLEN + j0 + row) * 1024;
            const __nv_bfloat16* slo = g_kvlo + ((size_t)b * KVLEN + j0 + row) * 1024;
            uint32_t doff = (uint32_t)(row * ATT_KSTR + seg) * 2;
            *(uint4*)(sm + AOFF_KH + doff) = *(const uint4*)(shi + h * DHD + seg);
            *(uint4*)(sm + AOFF_KL + doff) = *(const uint4*)(slo + h * DHD + seg);
            *(uint4*)(sm + AOFF_VH + doff) = *(const uint4*)(shi + 512 + h * DHD + seg);
            *(uint4*)(sm + AOFF_VL + doff) = *(const uint4*)(slo + 512 + h * DHD + seg);
        }
        if (t < JT) {
            int row = j0 + t;
            bool valid;
            if (row >= FF) valid = true;
            else {
                int mv = is_byte ? (int)mask8[b * FF + row] : mask32[b * FF + row];
                valid = (mv == 0);
            }
            vdf[t] = valid ? 1.f : 0.f;
        }
        __syncthreads();

        // phase 2: S = Q K^T (3-term), write SP[q][j]
        {
            const int wq = (wid & 3) * 16, wj = (wid >> 2) * 16;
            float c0[4] = {0.f, 0.f, 0.f, 0.f};
            float c1[4] = {0.f, 0.f, 0.f, 0.f};
            #pragma unroll
            for (int ks = 0; ks < 4; ks++) {
                uint32_t aqh[4], aql[4], bkh[4], bkl[4];
                uint32_t aoff = ((wq + (lane & 15)) * ATT_QSTR + ks * 16
                                 + (lane >> 4) * 8) * 2;
                ldsm_x4(aqh, sb + AOFF_QH + aoff);
                ldsm_x4(aql, sb + AOFF_QL + aoff);
                uint32_t boff = ((wj + (lane & 7) + ((lane >> 3) & 1) * 8) * ATT_KSTR
                                 + ks * 16 + (lane >> 4) * 8) * 2;
                ldsm_x4(bkh, sb + AOFF_KH + boff);
                ldsm_x4(bkl, sb + AOFF_KL + boff);
                mma16816(c0, aqh, bkh[0], bkh[2]);
                mma16816(c0, aqh, bkl[0], bkl[2]);
                mma16816(c0, aql, bkh[0], bkh[2]);
                mma16816(c1, aqh, bkh[1], bkh[3]);
                mma16816(c1, aqh, bkl[1], bkl[3]);
                mma16816(c1, aql, bkh[1], bkh[3]);
            }
            float* sp = (float*)(sm + AOFF_SP);
            int r = lane >> 2, cc = (lane & 3) * 2;
            *(float2*)&sp[(wq + r) * ATT_SSTR + wj + cc]      = make_float2(c0[0], c0[1]);
            *(float2*)&sp[(wq + r + 8) * ATT_SSTR + wj + cc]  = make_float2(c0[2], c0[3]);
            *(float2*)&sp[(wq + r) * ATT_SSTR + wj + 8 + cc]  = make_float2(c1[0], c1[1]);
            *(float2*)&sp[(wq + r + 8) * ATT_SSTR + wj + 8 + cc] = make_float2(c1[2], c1[3]);
        }
        __syncthreads();

        // phase 3: masked row max -> mnew, alpha
        if (t < 64) {
            const float* sp = (const float*)(sm + AOFF_SP) + t * ATT_SSTR;
            float mx = -1e30f;
            #pragma unroll
            for (int j = 0; j < JT; j++)
                mx = fmaxf(mx, (vdf[j] != 0.f) ? sp[j] : -1e30f);
            float mold = mf[t];
            float mnew = fmaxf(mold, mx);
            mnf[t] = mnew;
            alf[t] = __expf(mold - mnew);
            mf[t]  = mnew;
        }
        __syncthreads();

        // phase 4: P = exp(S - mnew) masked; split to Ph/Pl; scale acc by alpha
        {
            int q = t >> 2, jg = (t & 3) * 8;
            float* sp = (float*)(sm + AOFF_SP) + q * ATT_SSTR + jg;
            float mn = mnf[q];
            __nv_bfloat162* ph = (__nv_bfloat162*)(sm + AOFF_PH + (q * ATT_PSTR + jg) * 2);
            __nv_bfloat162* pl = (__nv_bfloat162*)(sm + AOFF_PL + (q * ATT_PSTR + jg) * 2);
            #pragma unroll
            for (int i = 0; i < 8; i += 2) {
                float e0 = (vdf[jg + i]     != 0.f) ? __expf(sp[i]     - mn) : 0.f;
                float e1 = (vdf[jg + i + 1] != 0.f) ? __expf(sp[i + 1] - mn) : 0.f;
                sp[i] = e0; sp[i + 1] = e1;
                __nv_bfloat162 hh = __floats2bfloat162_rn(e0, e1);
                __nv_bfloat162 ll = __floats2bfloat162_rn(e0 - __bfloat162float(hh.x),
                                                          e1 - __bfloat162float(hh.y));
                ph[i >> 1] = hh; pl[i >> 1] = ll;
            }
            const int wq = (wid & 3) * 16;
            float a1 = alf[wq + (lane >> 2)];
            float a2 = alf[wq + (lane >> 2) + 8];
            #pragma unroll
            for (int ni = 0; ni < 4; ni++) {
                acc[ni][0] *= a1; acc[ni][1] *= a1;
                acc[ni][2] *= a2; acc[ni][3] *= a2;
            }
        }
        __syncthreads();

        // phase 5: l update + O += P V (3-term)
        if (t < 64) {
            const float* sp = (const float*)(sm + AOFF_SP) + t * ATT_SSTR;
            float s = 0.f;
            #pragma unroll
            for (int j = 0; j < JT; j++) s += sp[j];
            lf[t] = lf[t] * alf[t] + s;
        }
        {
            const int wq = (wid & 3) * 16, wd = (wid >> 2) * 32;
            #pragma unroll
            for (int ks = 0; ks < 2; ks++) {
                uint32_t aph[4], apl[4], bvh0[4], bvh1[4], bvl0[4], bvl1[4];
                uint32_t aoff = ((wq + (lane & 15)) * ATT_PSTR + ks * 16
                                 + (lane >> 4) * 8) * 2;
                ldsm_x4(aph, sb + AOFF_PH + aoff);
                ldsm_x4(apl, sb + AOFF_PL + aoff);
                uint32_t vrow = ks * 16 + (lane & 15);
                uint32_t v0 = (vrow * ATT_KSTR + wd + (lane >> 4) * 8) * 2;
                uint32_t v1 = (vrow * ATT_KSTR + wd + 16 + (lane >> 4) * 8) * 2;
                ldsm_x4_trans(bvh0, sb + AOFF_VH + v0);
                ldsm_x4_trans(bvh1, sb + AOFF_VH + v1);
                ldsm_x4_trans(bvl0, sb + AOFF_VL + v0);
                ldsm_x4_trans(bvl1, sb + AOFF_VL + v1);
                mma16816(acc[0], aph, bvh0[0], bvh0[1]);
                mma16816(acc[0], aph, bvl0[0], bvl0[1]);
                mma16816(acc[0], apl, bvh0[0], bvh0[1]);
                mma16816(acc[1], aph, bvh0[2], bvh0[3]);
                mma16816(acc[1], aph, bvl0[2], bvl0[3]);
                mma16816(acc[1], apl, bvh0[2], bvh0[3]);
                mma16816(acc[2], aph, bvh1[0], bvh1[1]);
                mma16816(acc[2], aph, bvl1[0], bvl1[1]);
                mma16816(acc[2], apl, bvh1[0], bvh1[1]);
                mma16816(acc[3], aph, bvh1[2], bvh1[3]);
                mma16816(acc[3], aph, bvl1[2], bvl1[3]);
                mma16816(acc[3], apl, bvh1[2], bvh1[3]);
            }
        }
        __syncthreads();
    }

    // epilogue: write partials
    {
        const int wq = (wid & 3) * 16, wd = (wid >> 2) * 32;
        size_t pbase = ((((size_t)b * HH + h) * NSPLIT + split) * NLAT) * (size_t)DHD;
        int r = lane >> 2, cc = (lane & 3) * 2;
        #pragma unroll
        for (int ni = 0; ni < 4; ni++) {
            float* d0 = g_pacc + pbase + (size_t)(wq + r) * DHD + wd + ni * 8 + cc;
            float* d1 = g_pacc + pbase + (size_t)(wq + r + 8) * DHD + wd + ni * 8 + cc;
            *(float2*)d0 = make_float2(acc[ni][0], acc[ni][1]);
            *(float2*)d1 = make_float2(acc[ni][2], acc[ni][3]);
        }
    }
    if (t < 64) {
        size_t sbi = (((size_t)b * HH + h) * NSPLIT + split) * NLAT + t;
        g_pm[sbi] = mf[t];
        g_pl[sbi] = lf[t];
    }
}

// ---- pass B: combine split partials -> attn output (b, q, h*64+d) ----
__global__ __launch_bounds__(64) void attn_combine_kernel() {
    int q = blockIdx.x, h = blockIdx.y, b = blockIdx.z;
    int d = threadIdx.x;
    size_t sb = (((size_t)b * HH + h) * NSPLIT) * NLAT + q;
    float mg = -1e30f;
    #pragma unroll
    for (int s = 0; s < NSPLIT; s++) mg = fmaxf(mg, g_pm[sb + (size_t)s * NLAT]);
    float denom = 0.f, a = 0.f;
    #pragma unroll
    for (int s = 0; s < NSPLIT; s++) {
        float w = __expf(g_pm[sb + (size_t)s * NLAT] - mg);
        denom += g_pl[sb + (size_t)s * NLAT] * w;
        a += g_pacc[((((size_t)b * HH + h) * NSPLIT + s) * NLAT + q) * DHD + d] * w;
    }
    g_attnout[((size_t)b * NLAT + q) * INNER + h * DHD + d] = a / denom;
}

extern "C" void kernel_launch(void* const* d_in, const int* in_sizes, int n_in,
                              void* d_out, int out_size) {
    const float* x    = (const float*)d_in[0];
    const float* lat  = (const float*)d_in[1];
    const void*  mask = d_in[2];
    const float* gate = (const float*)d_in[3];
    const float* gm   = (const float*)d_in[4];
    const float* bm   = (const float*)d_in[5];
    const float* gl   = (const float*)d_in[6];
    const float* bl   = (const float*)d_in[7];
    const float* Wq   = (const float*)d_in[8];
    const float* Wk   = (const float*)d_in[9];
    const float* Wv   = (const float*)d_in[10];
    const float* Wout = (const float*)d_in[11];
    float* out = (float*)d_out;

    cudaFuncSetAttribute(kv_mma_kernel,
                         cudaFuncAttributeMaxDynamicSharedMemorySize, GEMM_SMEM);
    cudaFuncSetAttribute(attn_mma_kernel,
                         cudaFuncAttributeMaxDynamicSharedMemorySize, ATT_SMEM);

    // Launch order puts kv_mma_kernel 4th (the slot ncu's -s/-c window captures).
    ln_lat_kernel<<<BB * NLAT, 256>>>(lat, gl, bl, (const unsigned int*)mask);
    prep_a_kernel<<<MROWS, 256>>>(x, gm, bm, gate);
    prep_w_kernel<<<dim3(32, 32), 256>>>(Wk, Wv);
    kv_mma_kernel<<<dim3(8, 516), 128, GEMM_SMEM>>>();
    // Q = lat_ln @ Wq, scaled by DIM_HEAD^-0.5 = 0.125
    sgemm_kernel<<<dim3(INNER / 64, (BB * NLAT) / 64), 256>>>(
        Wq, nullptr, BB * NLAT, INNER, DD, DD, INNER, INNER, 0.125f, 0);
    attn_mma_kernel<<<dim3(NSPLIT, HH, BB), 256, ATT_SMEM>>>(mask);
    attn_combine_kernel<<<dim3(NLAT, HH, BB), 64>>>();
    sgemm_kernel<<<dim3(DD / 64, (BB * NLAT) / 64), 256>>>(
        Wout, out, BB * NLAT, DD, INNER, INNER, DD, DD, 1.0f, 1);
}

// round 11
// speedup vs baseline: 1.2871x; 1.2871x over previous
#include <cuda_runtime.h>
#include <cuda_bf16.h>
#include <cuda_fp16.h>
#include <cstdint>

// Problem dims (fixed by the dataset)
#define BB     8
#define FF     8192
#define NLAT   64
#define DD     1024
#define HH     8
#define DHD    64
#define INNER  512
#define KVLEN  (FF + NLAT)          // 8256
#define MROWS  (BB * KVLEN)         // 66048
#define NSPLIT 16
#define JT     32                    // kv tile in attention
#define NTILES (KVLEN / JT)          // 258
#define TPS    ((NTILES + NSPLIT - 1) / NSPLIT)  // 17
#define LN_EPS 1e-5f

// ---------------- family-safe PTX helpers (sm_80-era; no 'a'-features) ------
__device__ __forceinline__ uint32_t smem_u32(const void* p) {
    uint32_t a;
    asm("{ .reg .u64 t; cvta.to.shared.u64 t, %1; cvt.u32.u64 %0, t; }" : "=r"(a) : "l"(p));
    return a;
}
__device__ __forceinline__ void cp_async16(uint32_t dst, const void* src) {
    asm volatile("cp.async.cg.shared.global [%0], [%1], 16;" :: "r"(dst), "l"(src));
}
#define CP_COMMIT() asm volatile("cp.async.commit_group;" ::: "memory")
#define CP_WAIT(n)  asm volatile("cp.async.wait_group %0;" :: "n"(n) : "memory")

__device__ __forceinline__ void ldsm_x4(uint32_t* r, uint32_t addr) {
    asm volatile("ldmatrix.sync.aligned.m8n8.x4.shared.b16 {%0,%1,%2,%3}, [%4];"
        : "=r"(r[0]), "=r"(r[1]), "=r"(r[2]), "=r"(r[3]) : "r"(addr));
}
__device__ __forceinline__ void ldsm_x4_trans(uint32_t* r, uint32_t addr) {
    asm volatile("ldmatrix.sync.aligned.m8n8.x4.trans.shared.b16 {%0,%1,%2,%3}, [%4];"
        : "=r"(r[0]), "=r"(r[1]), "=r"(r[2]), "=r"(r[3]) : "r"(addr));
}
// fp16 mma
__device__ __forceinline__ void mma16816h(float* c, const uint32_t* a,
                                          uint32_t b0, uint32_t b1) {
    asm volatile(
        "mma.sync.aligned.m16n8k16.row.col.f32.f16.f16.f32 "
        "{%0,%1,%2,%3}, {%4,%5,%6,%7}, {%8,%9}, {%0,%1,%2,%3};"
        : "+f"(c[0]), "+f"(c[1]), "+f"(c[2]), "+f"(c[3])
        : "r"(a[0]), "r"(a[1]), "r"(a[2]), "r"(a[3]), "r"(b0), "r"(b1));
}

// -------- scratch (device globals; no allocations allowed) --------
__device__ float          g_lat_ln[BB * NLAT * DD];                       // 2 MB
__device__ __half         g_af[(size_t)MROWS * DD];                       // 135 MB (A fp16)
__device__ __half         g_bf[1024 * 1024];                              // 2 MB  [n][k] fp16
__device__ __half         g_kvf[(size_t)MROWS * 1024];                    // 135 MB (cols 0-511 K, 512-1023 V)
__device__ float          g_qmat[BB * NLAT * INNER];                      // 1 MB
__device__ float          g_attnout[BB * NLAT * INNER];                   // 1 MB
__device__ float          g_pacc[(size_t)BB * HH * NSPLIT * NLAT * DHD];  // 16.8 MB
__device__ float          g_pm[BB * HH * NSPLIT * NLAT];
__device__ float          g_pl[BB * HH * NSPLIT * NLAT];
__device__ int            g_mask_is_byte;

// ---- LayerNorm of latents + (block 0) mask dtype detection ----
__global__ __launch_bounds__(256) void ln_lat_kernel(const float* __restrict__ lat,
                                                     const float* __restrict__ gamma,
                                                     const float* __restrict__ beta,
                                                     const unsigned int* __restrict__ mask_w) {
    int row = blockIdx.x;
    int t = threadIdx.x;
    if (row == 0 && t == 0) {
        unsigned int acc = 0;
        #pragma unroll
        for (int i = 0; i < 64; i++) acc |= mask_w[i];
        g_mask_is_byte = (acc > 1u) ? 1 : 0;
    }
    float4 v = ((const float4*)(lat + (size_t)row * DD))[t];
    __shared__ float rs[256], rq[256];
    rs[t] = v.x + v.y + v.z + v.w;
    rq[t] = v.x*v.x + v.y*v.y + v.z*v.z + v.w*v.w;
    __syncthreads();
    for (int off = 128; off > 0; off >>= 1) {
        if (t < off) { rs[t] += rs[t + off]; rq[t] += rq[t + off]; }
        __syncthreads();
    }
    float mu   = rs[0] * (1.f / DD);
    float var  = rq[0] * (1.f / DD) - mu * mu;
    float rstd = rsqrtf(var + LN_EPS);
    float4 gv = ((const float4*)gamma)[t];
    float4 bv = ((const float4*)beta)[t];
    float4 o;
    o.x = (v.x - mu) * rstd * gv.x + bv.x;
    o.y = (v.y - mu) * rstd * gv.y + bv.y;
    o.z = (v.z - mu) * rstd * gv.z + bv.z;
    o.w = (v.w - mu) * rstd * gv.w + bv.w;
    ((float4*)(g_lat_ln + (size_t)row * DD))[t] = o;
}

// ---- fused LN + fp16 store of the KV input matrix A ----
__global__ __launch_bounds__(256) void prep_a_kernel(const float* __restrict__ x,
                                                     const float* __restrict__ gm_,
                                                     const float* __restrict__ bm_,
                                                     const float* __restrict__ gate_p) {
    int row = blockIdx.x;                 // 0..MROWS-1
    int b = row / KVLEN;
    int r = row - b * KVLEN;
    int t = threadIdx.x;
    float4 y;
    if (r < FF) {
        float4 v = ((const float4*)(x + ((size_t)b * FF + r) * DD))[t];
        __shared__ float rs[256], rq[256];
        rs[t] = v.x + v.y + v.z + v.w;
        rq[t] = v.x*v.x + v.y*v.y + v.z*v.z + v.w*v.w;
        __syncthreads();
        for (int off = 128; off > 0; off >>= 1) {
            if (t < off) { rs[t] += rs[t + off]; rq[t] += rq[t + off]; }
            __syncthreads();
        }
        float mu   = rs[0] * (1.f / DD);
        float var  = rq[0] * (1.f / DD) - mu * mu;
        float rstd = rsqrtf(var + LN_EPS);
        float4 gv = ((const float4*)gm_)[t];
        float4 bv = ((const float4*)bm_)[t];
        y.x = (v.x - mu) * rstd * gv.x + bv.x;
        y.y = (v.y - mu) * rstd * gv.y + bv.y;
        y.z = (v.z - mu) * rstd * gv.z + bv.z;
        y.w = (v.w - mu) * rstd * gv.w + bv.w;
    } else {
        float4 v = ((const float4*)(g_lat_ln + ((size_t)b * NLAT + (r - FF)) * DD))[t];
        float gate = gate_p[0];
        y.x = v.x * gate; y.y = v.y * gate; y.z = v.z * gate; y.w = v.w * gate;
    }
    __half2* d = (__half2*)(g_af + (size_t)row * DD) + 2 * t;
    d[0] = __floats2half2_rn(y.x, y.y);
    d[1] = __floats2half2_rn(y.z, y.w);
}

// ---- transpose [Wk|Wv] (k-major [1024][512] each) into B[n][k] fp16 ----
__global__ __launch_bounds__(256) void prep_w_kernel(const float* __restrict__ Wk,
                                                     const float* __restrict__ Wv) {
    __shared__ float tile[32][33];
    int n0 = blockIdx.x * 32;           // 0..1023 (n of concat)
    int k0 = blockIdx.y * 32;
    int tx = threadIdx.x & 31, ty = threadIdx.x >> 5;  // 32 x 8
    const float* W = (n0 < 512) ? Wk : Wv;
    int nn0 = (n0 < 512) ? n0 : (n0 - 512);
    for (int i = ty; i < 32; i += 8)
        tile[i][tx] = W[(size_t)(k0 + i) * 512 + nn0 + tx];
    __syncthreads();
    for (int i = ty; i < 32; i += 8) {
        float v = tile[tx][i];          // = W[k0+tx][nn0+i]
        g_bf[(size_t)(n0 + i) * 1024 + k0 + tx] = __float2half_rn(v);
    }
}

// ---- HMMA (mma.sync fp16, 1-term) K/V projection: kv = A @ B^T ----
// R9-proven config: BM=128, BN=128, BK=32, 256 thr = 8 warps (4m x 2n),
// warp tile 32x64, 122 regs, 2 CTAs/SM. (R10's 64x64 tile hit 234 regs ->
// occupancy 12% and regressed; warps/SM is the binding resource here.)
// 4-stage cp.async pipeline, stage = {A, B} = 20480 B.
#define AS_STRIDE_H 40                      // halves per SMEM row
#define MAT_BYTES   (128 * AS_STRIDE_H * 2) // 10240 per matrix tile
#define STG_BYTES   (2 * MAT_BYTES)         // 20480 per stage (A, B)
#define NSTAGE      4
#define GEMM_SMEM   (NSTAGE * STG_BYTES)    // 81920
#define NCHUNK      32

__global__ __launch_bounds__(256, 2) void kv_mma_kernel() {
    extern __shared__ char smem[];
    const uint32_t sbase = smem_u32(smem);
    const int t = threadIdx.x;
    const int wid = t >> 5, lane = t & 31;
    const int ntile = blockIdx.x;            // 0..7
    const int mtile = blockIdx.y;            // 0..515
    const size_t arow0 = (size_t)mtile * 128;
    const int    brow0 = ntile * 128;

    // global load assignment: row r_ld, two consecutive 16B segs
    const int r_ld = t >> 1;
    const int seg0 = (t & 1) * 2;            // 0 or 2 (of 4 segs/row)
    const __half* gA = g_af + (arow0 + r_ld) * 1024 + seg0 * 8;
    const __half* gB = g_bf + (size_t)(brow0 + r_ld) * 1024 + seg0 * 8;
    const uint32_t sAdst = sbase + r_ld * 80 + seg0 * 16;

    #define LOAD_CHUNK(chunk, stg_) do {                                       \
        uint32_t sb_ = sAdst + (stg_) * STG_BYTES;                             \
        int ko_ = (chunk) * 32;                                                \
        cp_async16(sb_,                  gA + ko_);                            \
        cp_async16(sb_ + 16,             gA + ko_ + 8);                        \
        cp_async16(sb_ + MAT_BYTES,      gB + ko_);                            \
        cp_async16(sb_ + MAT_BYTES + 16, gB + ko_ + 8);                        \
    } while (0)

    // warp tile: wm in {0,32,64,96}, wn in {0,64}
    const int wm = (wid & 3) * 32;
    const int wn = (wid >> 2) * 64;

    const int a_off_h = (wm + (lane & 15)) * AS_STRIDE_H + (lane >> 4) * 8;
    const int b_off_h = (wn + (lane & 7) + ((lane >> 3) & 1) * 8) * AS_STRIDE_H
                        + (lane >> 4) * 8;

    float acc[2][8][4];
    #pragma unroll
    for (int i = 0; i < 2; i++)
        #pragma unroll
        for (int j = 0; j < 8; j++)
            #pragma unroll
            for (int c = 0; c < 4; c++) acc[i][j][c] = 0.f;

    LOAD_CHUNK(0, 0); CP_COMMIT();
    LOAD_CHUNK(1, 1); CP_COMMIT();
    LOAD_CHUNK(2, 2); CP_COMMIT();

    int st = 0;  // stage of current chunk
    for (int chunk = 0; chunk < NCHUNK; chunk++) {
        if (chunk < NCHUNK - 2)       { CP_WAIT(2); }
        else if (chunk == NCHUNK - 2) { CP_WAIT(1); }
        else                          { CP_WAIT(0); }
        __syncthreads();   // also protects WAR on the stage being refilled
        if (chunk + 3 < NCHUNK) {
            int stn = st + 3; if (stn >= NSTAGE) stn -= NSTAGE;
            LOAD_CHUNK(chunk + 3, stn);
            CP_COMMIT();
        }

        const uint32_t stg = sbase + st * STG_BYTES;
        #pragma unroll
        for (int ks = 0; ks < 2; ks++) {
            uint32_t a[2][4];
            #pragma unroll
            for (int mi = 0; mi < 2; mi++) {
                uint32_t ao = stg + (a_off_h + mi * 16 * AS_STRIDE_H + ks * 16) * 2;
                ldsm_x4(a[mi], ao);
            }
            #pragma unroll
            for (int nip = 0; nip < 4; nip++) {
                uint32_t bb[4];
                uint32_t bo = stg + MAT_BYTES
                            + (b_off_h + nip * 16 * AS_STRIDE_H + ks * 16) * 2;
                ldsm_x4(bb, bo);
                #pragma unroll
                for (int mi = 0; mi < 2; mi++) {
                    mma16816h(acc[mi][nip * 2],     a[mi], bb[0], bb[2]);
                    mma16816h(acc[mi][nip * 2 + 1], a[mi], bb[1], bb[3]);
                }
            }
        }
        if (++st == NSTAGE) st = 0;
    }

    // epilogue: write kv as single fp16
    const int col0 = ntile * 128 + wn + (lane & 3) * 2;
    #pragma unroll
    for (int mi = 0; mi < 2; mi++) {
        size_t row = arow0 + wm + mi * 16 + (lane >> 2);
        #pragma unroll
        for (int ni = 0; ni < 8; ni++) {
            size_t o0 = row * 1024 + col0 + ni * 8;
            size_t o1 = (row + 8) * 1024 + col0 + ni * 8;
            *(__half2*)(g_kvf + o0) = __floats2half2_rn(acc[mi][ni][0], acc[mi][ni][1]);
            *(__half2*)(g_kvf + o1) = __floats2half2_rn(acc[mi][ni][2], acc[mi][ni][3]);
        }
    }
}

// ---- generic small sgemm (mode 0: Q proj, mode 1: out proj) ----
__global__ __launch_bounds__(256) void sgemm_kernel(const float* __restrict__ Bmat,
                                                    float* __restrict__ Cext,
                                                    int M, int N, int K,
                                                    int lda, int ldb, int ldc,
                                                    float alpha, int mode) {
    const float* A = (mode == 0) ? g_lat_ln : g_attnout;
    float* C = (mode == 0) ? g_qmat : Cext;
    __shared__ float As[16][65];
    __shared__ float Bs[16][65];
    int t = threadIdx.x;
    int tx = t & 15, ty = t >> 4;
    int n0 = blockIdx.x * 64;
    int m0 = blockIdx.y * 64;
    float acc[4][4] = {};
    for (int k0 = 0; k0 < K; k0 += 16) {
        #pragma unroll
        for (int l = 0; l < 4; l++) {
            int idx = t + l * 256;
            int row = idx >> 4, kk = idx & 15;
            As[kk][row] = A[(size_t)(m0 + row) * lda + k0 + kk];
        }
        #pragma unroll
        for (int l = 0; l < 4; l++) {
            int idx = t + l * 256;
            int kk = idx >> 6, col = idx & 63;
            Bs[kk][col] = Bmat[(size_t)(k0 + kk) * ldb + n0 + col];
        }
        __syncthreads();
        #pragma unroll
        for (int kk = 0; kk < 16; kk++) {
            float a[4], bb[4];
            #pragma unroll
            for (int i = 0; i < 4; i++) a[i]  = As[kk][ty * 4 + i];
            #pragma unroll
            for (int j = 0; j < 4; j++) bb[j] = Bs[kk][tx * 4 + j];
            #pragma unroll
            for (int i = 0; i < 4; i++)
                #pragma unroll
                for (int j = 0; j < 4; j++)
                    acc[i][j] = fmaf(a[i], bb[j], acc[i][j]);
        }
        __syncthreads();
    }
    #pragma unroll
    for (int i = 0; i < 4; i++)
        #pragma unroll
        for (int j = 0; j < 4; j++)
            C[(size_t)(m0 + ty * 4 + i) * ldc + n0 + tx * 4 + j] = alpha * acc[i][j];
}

// ---- split-KV flash attention, fp16 HMMA ----
// Q split fp16 hi/lo (exact to 2^-22); K,V single fp16; P split fp16 hi/lo.
#define ATT_QSTR 72
#define ATT_KSTR 72
#define ATT_PSTR 40
#define ATT_SSTR 40
#define AOFF_QH 0
#define AOFF_QL 9216
#define AOFF_K  18432
#define AOFF_V  23040
#define AOFF_SP 27648
#define AOFF_PH 37888
#define AOFF_PL 43008
#define AOFF_M  48128
#define AOFF_L  48384
#define AOFF_AL 48640
#define AOFF_MN 48896
#define AOFF_VD 49152
#define ATT_SMEM 49280

__global__ __launch_bounds__(256) void attn_mma_kernel(const void* __restrict__ mask_raw) {
    extern __shared__ char sm[];
    const uint32_t sb = smem_u32(sm);
    const int split = blockIdx.x, h = blockIdx.y, b = blockIdx.z;
    const int t = threadIdx.x, wid = t >> 5, lane = t & 31;
    const unsigned char* mask8 = (const unsigned char*)mask_raw;
    const int*           mask32 = (const int*)mask_raw;
    const int is_byte = g_mask_is_byte;

    float* mf  = (float*)(sm + AOFF_M);
    float* lf  = (float*)(sm + AOFF_L);
    float* alf = (float*)(sm + AOFF_AL);
    float* mnf = (float*)(sm + AOFF_MN);
    float* vdf = (float*)(sm + AOFF_VD);

    // prologue: load+split Q slice (64q x 64d) to Qh/Ql (fp16 hi/lo)
    {
        int q = t >> 2, dg = (t & 3) * 16;
        const float4* src = (const float4*)(g_qmat + ((size_t)(b * NLAT + q)) * INNER
                                            + h * DHD + dg);
        __half2* qh = (__half2*)(sm + AOFF_QH + (q * ATT_QSTR + dg) * 2);
        __half2* ql = (__half2*)(sm + AOFF_QL + (q * ATT_QSTR + dg) * 2);
        #pragma unroll
        for (int i = 0; i < 4; i++) {
            float4 v = src[i];
            __half2 h01 = __floats2half2_rn(v.x, v.y);
            __half2 h23 = __floats2half2_rn(v.z, v.w);
            __half2 l01 = __floats2half2_rn(v.x - __half2float(__low2half(h01)),
                                            v.y - __half2float(__high2half(h01)));
            __half2 l23 = __floats2half2_rn(v.z - __half2float(__low2half(h23)),
                                            v.w - __half2float(__high2half(h23)));
            qh[i * 2] = h01; qh[i * 2 + 1] = h23;
            ql[i * 2] = l01; ql[i * 2 + 1] = l23;
        }
    }
    if (t < 64) { mf[t] = -1e30f; lf[t] = 0.f; }

    float acc[4][4];
    #pragma unroll
    for (int i = 0; i < 4; i++)
        #pragma unroll
        for (int j = 0; j < 4; j++) acc[i][j] = 0.f;

    const int t0 = split * TPS;
    int tcnt = NTILES - t0;
    if (tcnt > TPS) tcnt = TPS;
    if (tcnt < 0) tcnt = 0;
    __syncthreads();

    for (int it = 0; it < tcnt; it++) {
        const int j0 = (t0 + it) * JT;
        // phase 1: K/V fp16 tiles: 32 rows x 8 segs, 1 seg/thread per array
        {
            int row = t >> 3;              // 0..31
            int seg = (t & 7) * 8;         // halves
            const __half* src = g_kvf + ((size_t)b * KVLEN + j0 + row) * 1024;
            uint32_t doff = (uint32_t)(row * ATT_KSTR + seg) * 2;
            *(uint4*)(sm + AOFF_K + doff) = *(const uint4*)(src + h * DHD + seg);
            *(uint4*)(sm + AOFF_V + doff) = *(const uint4*)(src + 512 + h * DHD + seg);
        }
        if (t < JT) {
            int row = j0 + t;
            bool valid;
            if (row >= FF) valid = true;
            else {
                int mv = is_byte ? (int)mask8[b * FF + row] : mask32[b * FF + row];
                valid = (mv == 0);
            }
            vdf[t] = valid ? 1.f : 0.f;
        }
        __syncthreads();

        // phase 2: S = Q K^T (2-term fp16), write SP[q][j]
        {
            const int wq = (wid & 3) * 16, wj = (wid >> 2) * 16;
            float c0[4] = {0.f, 0.f, 0.f, 0.f};
            float c1[4] = {0.f, 0.f, 0.f, 0.f};
            #pragma unroll
            for (int ks = 0; ks < 4; ks++) {
                uint32_t aqh[4], aql[4], bk[4];
                uint32_t aoff = ((wq + (lane & 15)) * ATT_QSTR + ks * 16
                                 + (lane >> 4) * 8) * 2;
                ldsm_x4(aqh, sb + AOFF_QH + aoff);
                ldsm_x4(aql, sb + AOFF_QL + aoff);
                uint32_t boff = ((wj + (lane & 7) + ((lane >> 3) & 1) * 8) * ATT_KSTR
                                 + ks * 16 + (lane >> 4) * 8) * 2;
                ldsm_x4(bk, sb + AOFF_K + boff);
                mma16816h(c0, aqh, bk[0], bk[2]);
                mma16816h(c0, aql, bk[0], bk[2]);
                mma16816h(c1, aqh, bk[1], bk[3]);
                mma16816h(c1, aql, bk[1], bk[3]);
            }
            float* sp = (float*)(sm + AOFF_SP);
            int r = lane >> 2, cc = (lane & 3) * 2;
            *(float2*)&sp[(wq + r) * ATT_SSTR + wj + cc]      = make_float2(c0[0], c0[1]);
            *(float2*)&sp[(wq + r + 8) * ATT_SSTR + wj + cc]  = make_float2(c0[2], c0[3]);
            *(float2*)&sp[(wq + r) * ATT_SSTR + wj + 8 + cc]  = make_float2(c1[0], c1[1]);
            *(float2*)&sp[(wq + r + 8) * ATT_SSTR + wj + 8 + cc] = make_float2(c1[2], c1[3]);
        }
        __syncthreads();

        // phase 3: masked row max -> mnew, alpha
        if (t < 64) {
            const float* sp = (const float*)(sm + AOFF_SP) + t * ATT_SSTR;
            float mx = -1e30f;
            #pragma unroll
            for (int j = 0; j < JT; j++)
                mx = fmaxf(mx, (vdf[j] != 0.f) ? sp[j] : -1e30f);
            float mold = mf[t];
            float mnew = fmaxf(mold, mx);
            mnf[t] = mnew;
            alf[t] = __expf(mold - mnew);
            mf[t]  = mnew;
        }
        __syncthreads();

        // phase 4: P = exp(S - mnew) masked; split to Ph/Pl (fp16); acc *= alpha
        {
            int q = t >> 2, jg = (t & 3) * 8;
            float* sp = (float*)(sm + AOFF_SP) + q * ATT_SSTR + jg;
            float mn = mnf[q];
            __half2* ph = (__half2*)(sm + AOFF_PH + (q * ATT_PSTR + jg) * 2);
            __half2* pl = (__half2*)(sm + AOFF_PL + (q * ATT_PSTR + jg) * 2);
            #pragma unroll
            for (int i = 0; i < 8; i += 2) {
                float e0 = (vdf[jg + i]     != 0.f) ? __expf(sp[i]     - mn) : 0.f;
                float e1 = (vdf[jg + i + 1] != 0.f) ? __expf(sp[i + 1] - mn) : 0.f;
                sp[i] = e0; sp[i + 1] = e1;
                __half2 hh = __floats2half2_rn(e0, e1);
                __half2 ll = __floats2half2_rn(e0 - __half2float(__low2half(hh)),
                                               e1 - __half2float(__high2half(hh)));
                ph[i >> 1] = hh; pl[i >> 1] = ll;
            }
            const int wq = (wid & 3) * 16;
            float a1 = alf[wq + (lane >> 2)];
            float a2 = alf[wq + (lane >> 2) + 8];
            #pragma unroll
            for (int ni = 0; ni < 4; ni++) {
                acc[ni][0] *= a1; acc[ni][1] *= a1;
                acc[ni][2] *= a2; acc[ni][3] *= a2;
            }
        }
        __syncthreads();

        // phase 5: l update + O += P V (2-term fp16)
        if (t < 64) {
            const float* sp = (const float*)(sm + AOFF_SP) + t * ATT_SSTR;
            float s = 0.f;
            #pragma unroll
            for (int j = 0; j < JT; j++) s += sp[j];
            lf[t] = lf[t] * alf[t] + s;
        }
        {
            const int wq = (wid & 3) * 16, wd = (wid >> 2) * 32;
            #pragma unroll
            for (int ks = 0; ks < 2; ks++) {
                uint32_t aph[4], apl[4], bv0[4], bv1[4];
                uint32_t aoff = ((wq + (lane & 15)) * ATT_PSTR + ks * 16
                                 + (lane >> 4) * 8) * 2;
                ldsm_x4(aph, sb + AOFF_PH + aoff);
                ldsm_x4(apl, sb + AOFF_PL + aoff);
                uint32_t vrow = ks * 16 + (lane & 15);
                uint32_t v0 = (vrow * ATT_KSTR + wd + (lane >> 4) * 8) * 2;
                uint32_t v1 = (vrow * ATT_KSTR + wd + 16 + (lane >> 4) * 8) * 2;
                ldsm_x4_trans(bv0, sb + AOFF_V + v0);
                ldsm_x4_trans(bv1, sb + AOFF_V + v1);
                mma16816h(acc[0], aph, bv0[0], bv0[1]);
                mma16816h(acc[0], apl, bv0[0], bv0[1]);
                mma16816h(acc[1], aph, bv0[2], bv0[3]);
                mma16816h(acc[1], apl, bv0[2], bv0[3]);
                mma16816h(acc[2], aph, bv1[0], bv1[1]);
                mma16816h(acc[2], apl, bv1[0], bv1[1]);
                mma16816h(acc[3], aph, bv1[2], bv1[3]);
                mma16816h(acc[3], apl, bv1[2], bv1[3]);
            }
        }
        __syncthreads();
    }

    // epilogue: write partials
    {
        const int wq = (wid & 3) * 16, wd = (wid >> 2) * 32;
        size_t pbase = ((((size_t)b * HH + h) * NSPLIT + split) * NLAT) * (size_t)DHD;
        int r = lane >> 2, cc = (lane & 3) * 2;
        #pragma unroll
        for (int ni = 0; ni < 4; ni++) {
            float* d0 = g_pacc + pbase + (size_t)(wq + r) * DHD + wd + ni * 8 + cc;
            float* d1 = g_pacc + pbase + (size_t)(wq + r + 8) * DHD + wd + ni * 8 + cc;
            *(float2*)d0 = make_float2(acc[ni][0], acc[ni][1]);
            *(float2*)d1 = make_float2(acc[ni][2], acc[ni][3]);
        }
    }
    if (t < 64) {
        size_t sbi = (((size_t)b * HH + h) * NSPLIT + split) * NLAT + t;
        g_pm[sbi] = mf[t];
        g_pl[sbi] = lf[t];
    }
}

// ---- pass B: combine split partials -> attn output (b, q, h*64+d) ----
__global__ __launch_bounds__(64) void attn_combine_kernel() {
    int q = blockIdx.x, h = blockIdx.y, b = blockIdx.z;
    int d = threadIdx.x;
    size_t sb = (((size_t)b * HH + h) * NSPLIT) * NLAT + q;
    float mg = -1e30f;
    #pragma unroll
    for (int s = 0; s < NSPLIT; s++) mg = fmaxf(mg, g_pm[sb + (size_t)s * NLAT]);
    float denom = 0.f, a = 0.f;
    #pragma unroll
    for (int s = 0; s < NSPLIT; s++) {
        float w = __expf(g_pm[sb + (size_t)s * NLAT] - mg);
        denom += g_pl[sb + (size_t)s * NLAT] * w;
        a += g_pacc[((((size_t)b * HH + h) * NSPLIT + s) * NLAT + q) * DHD + d] * w;
    }
    g_attnout[((size_t)b * NLAT + q) * INNER + h * DHD + d] = a / denom;
}

extern "C" void kernel_launch(void* const* d_in, const int* in_sizes, int n_in,
                              void* d_out, int out_size) {
    const float* x    = (const float*)d_in[0];
    const float* lat  = (const float*)d_in[1];
    const void*  mask = d_in[2];
    const float* gate = (const float*)d_in[3];
    const float* gm   = (const float*)d_in[4];
    const float* bm   = (const float*)d_in[5];
    const float* gl   = (const float*)d_in[6];
    const float* bl   = (const float*)d_in[7];
    const float* Wq   = (const float*)d_in[8];
    const float* Wk   = (const float*)d_in[9];
    const float* Wv   = (const float*)d_in[10];
    const float* Wout = (const float*)d_in[11];
    float* out = (float*)d_out;

    cudaFuncSetAttribute(kv_mma_kernel,
                         cudaFuncAttributeMaxDynamicSharedMemorySize, GEMM_SMEM);
    cudaFuncSetAttribute(attn_mma_kernel,
                         cudaFuncAttributeMaxDynamicSharedMemorySize, ATT_SMEM);

    // Launch order puts kv_mma_kernel 4th (the slot ncu's -s/-c window captures).
    ln_lat_kernel<<<BB * NLAT, 256>>>(lat, gl, bl, (const unsigned int*)mask);
    prep_a_kernel<<<MROWS, 256>>>(x, gm, bm, gate);
    prep_w_kernel<<<dim3(32, 32), 256>>>(Wk, Wv);
    kv_mma_kernel<<<dim3(8, 516), 256, GEMM_SMEM>>>();
    // Q = lat_ln @ Wq, scaled by DIM_HEAD^-0.5 = 0.125
    sgemm_kernel<<<dim3(INNER / 64, (BB * NLAT) / 64), 256>>>(
        Wq, nullptr, BB * NLAT, INNER, DD, DD, INNER, INNER, 0.125f, 0);
    attn_mma_kernel<<<dim3(NSPLIT, HH, BB), 256, ATT_SMEM>>>(mask);
    attn_combine_kernel<<<dim3(NLAT, HH, BB), 64>>>();
    sgemm_kernel<<<dim3(DD / 64, (BB * NLAT) / 64), 256>>>(
        Wout, out, BB * NLAT, DD, INNER, INNER, DD, DD, 1.0f, 1);
}

// round 12
// speedup vs baseline: 1.3234x; 1.0282x over previous
#include <cuda_runtime.h>
#include <cuda_bf16.h>
#include <cuda_fp16.h>
#include <cstdint>

// Problem dims (fixed by the dataset)
#define BB     8
#define FF     8192
#define NLAT   64
#define DD     1024
#define HH     8
#define DHD    64
#define INNER  512
#define KVLEN  (FF + NLAT)          // 8256
#define MROWS  (BB * KVLEN)         // 66048
#define NSPLIT 16
#define JT     32                    // kv tile in attention
#define NTILES (KVLEN / JT)          // 258
#define TPS    ((NTILES + NSPLIT - 1) / NSPLIT)  // 17
#define LN_EPS 1e-5f

// ---------------- family-safe PTX helpers (sm_80-era; no 'a'-features) ------
__device__ __forceinline__ uint32_t smem_u32(const void* p) {
    uint32_t a;
    asm("{ .reg .u64 t; cvta.to.shared.u64 t, %1; cvt.u32.u64 %0, t; }" : "=r"(a) : "l"(p));
    return a;
}
__device__ __forceinline__ void cp_async16(uint32_t dst, const void* src) {
    asm volatile("cp.async.cg.shared.global [%0], [%1], 16;" :: "r"(dst), "l"(src));
}
#define CP_COMMIT() asm volatile("cp.async.commit_group;" ::: "memory")
#define CP_WAIT(n)  asm volatile("cp.async.wait_group %0;" :: "n"(n) : "memory")

__device__ __forceinline__ void ldsm_x4(uint32_t* r, uint32_t addr) {
    asm volatile("ldmatrix.sync.aligned.m8n8.x4.shared.b16 {%0,%1,%2,%3}, [%4];"
        : "=r"(r[0]), "=r"(r[1]), "=r"(r[2]), "=r"(r[3]) : "r"(addr));
}
__device__ __forceinline__ void ldsm_x4_trans(uint32_t* r, uint32_t addr) {
    asm volatile("ldmatrix.sync.aligned.m8n8.x4.trans.shared.b16 {%0,%1,%2,%3}, [%4];"
        : "=r"(r[0]), "=r"(r[1]), "=r"(r[2]), "=r"(r[3]) : "r"(addr));
}
// fp16 mma
__device__ __forceinline__ void mma16816h(float* c, const uint32_t* a,
                                          uint32_t b0, uint32_t b1) {
    asm volatile(
        "mma.sync.aligned.m16n8k16.row.col.f32.f16.f16.f32 "
        "{%0,%1,%2,%3}, {%4,%5,%6,%7}, {%8,%9}, {%0,%1,%2,%3};"
        : "+f"(c[0]), "+f"(c[1]), "+f"(c[2]), "+f"(c[3])
        : "r"(a[0]), "r"(a[1]), "r"(a[2]), "r"(a[3]), "r"(b0), "r"(b1));
}

// -------- scratch (device globals; no allocations allowed) --------
__device__ float          g_lat_ln[BB * NLAT * DD];                       // 2 MB
__device__ __half         g_af[(size_t)MROWS * DD];                       // 135 MB (A fp16)
__device__ __half         g_bf[1024 * 1024];                              // 2 MB  [n][k] fp16
__device__ __half         g_kvf[(size_t)MROWS * 1024];                    // 135 MB (cols 0-511 K, 512-1023 V)
__device__ float          g_qmat[BB * NLAT * INNER];                      // 1 MB
__device__ float          g_attnout[BB * NLAT * INNER];                   // 1 MB
__device__ float          g_pacc[(size_t)BB * HH * NSPLIT * NLAT * DHD];  // 16.8 MB
__device__ float          g_pm[BB * HH * NSPLIT * NLAT];
__device__ float          g_pl[BB * HH * NSPLIT * NLAT];
__device__ int            g_mask_is_byte;

// ---- LayerNorm of latents + (block 0) mask dtype detection ----
__global__ __launch_bounds__(256) void ln_lat_kernel(const float* __restrict__ lat,
                                                     const float* __restrict__ gamma,
                                                     const float* __restrict__ beta,
                                                     const unsigned int* __restrict__ mask_w) {
    int row = blockIdx.x;
    int t = threadIdx.x;
    if (row == 0 && t == 0) {
        unsigned int acc = 0;
        #pragma unroll
        for (int i = 0; i < 64; i++) acc |= mask_w[i];
        g_mask_is_byte = (acc > 1u) ? 1 : 0;
    }
    float4 v = ((const float4*)(lat + (size_t)row * DD))[t];
    __shared__ float rs[256], rq[256];
    rs[t] = v.x + v.y + v.z + v.w;
    rq[t] = v.x*v.x + v.y*v.y + v.z*v.z + v.w*v.w;
    __syncthreads();
    for (int off = 128; off > 0; off >>= 1) {
        if (t < off) { rs[t] += rs[t + off]; rq[t] += rq[t + off]; }
        __syncthreads();
    }
    float mu   = rs[0] * (1.f / DD);
    float var  = rq[0] * (1.f / DD) - mu * mu;
    float rstd = rsqrtf(var + LN_EPS);
    float4 gv = ((const float4*)gamma)[t];
    float4 bv = ((const float4*)beta)[t];
    float4 o;
    o.x = (v.x - mu) * rstd * gv.x + bv.x;
    o.y = (v.y - mu) * rstd * gv.y + bv.y;
    o.z = (v.z - mu) * rstd * gv.z + bv.z;
    o.w = (v.w - mu) * rstd * gv.w + bv.w;
    ((float4*)(g_lat_ln + (size_t)row * DD))[t] = o;
}

// ---- fused LN + fp16 store of A: one row per warp, shuffle reduction ----
__global__ __launch_bounds__(256) void prep_a_kernel(const float* __restrict__ x,
                                                     const float* __restrict__ gm_,
                                                     const float* __restrict__ bm_,
                                                     const float* __restrict__ gate_p) {
    int wid = threadIdx.x >> 5, lane = threadIdx.x & 31;
    int row = blockIdx.x * 8 + wid;       // 0..MROWS-1 (grid = MROWS/8)
    int b = row / KVLEN;
    int r = row - b * KVLEN;
    float4 v[8];
    const float4* src;
    if (r < FF) src = (const float4*)(x + ((size_t)b * FF + r) * DD);
    else        src = (const float4*)(g_lat_ln + ((size_t)b * NLAT + (r - FF)) * DD);
    #pragma unroll
    for (int i = 0; i < 8; i++) v[i] = src[lane + 32 * i];

    if (r < FF) {
        float s = 0.f, q = 0.f;
        #pragma unroll
        for (int i = 0; i < 8; i++) {
            s += v[i].x + v[i].y + v[i].z + v[i].w;
            q += v[i].x*v[i].x + v[i].y*v[i].y + v[i].z*v[i].z + v[i].w*v[i].w;
        }
        #pragma unroll
        for (int off = 16; off > 0; off >>= 1) {
            s += __shfl_xor_sync(0xffffffffu, s, off);
            q += __shfl_xor_sync(0xffffffffu, q, off);
        }
        float mu   = s * (1.f / DD);
        float var  = q * (1.f / DD) - mu * mu;
        float rstd = rsqrtf(var + LN_EPS);
        #pragma unroll
        for (int i = 0; i < 8; i++) {
            float4 gv = ((const float4*)gm_)[lane + 32 * i];
            float4 bv = ((const float4*)bm_)[lane + 32 * i];
            v[i].x = (v[i].x - mu) * rstd * gv.x + bv.x;
            v[i].y = (v[i].y - mu) * rstd * gv.y + bv.y;
            v[i].z = (v[i].z - mu) * rstd * gv.z + bv.z;
            v[i].w = (v[i].w - mu) * rstd * gv.w + bv.w;
        }
    } else {
        float gate = gate_p[0];
        #pragma unroll
        for (int i = 0; i < 8; i++) {
            v[i].x *= gate; v[i].y *= gate; v[i].z *= gate; v[i].w *= gate;
        }
    }
    uint2* dst = (uint2*)(g_af + (size_t)row * DD);
    #pragma unroll
    for (int i = 0; i < 8; i++) {
        __half2 h01 = __floats2half2_rn(v[i].x, v[i].y);
        __half2 h23 = __floats2half2_rn(v[i].z, v[i].w);
        uint2 u;
        u.x = *(uint32_t*)&h01;
        u.y = *(uint32_t*)&h23;
        dst[lane + 32 * i] = u;
    }
}

// ---- transpose [Wk|Wv] (k-major [1024][512] each) into B[n][k] fp16 ----
__global__ __launch_bounds__(256) void prep_w_kernel(const float* __restrict__ Wk,
                                                     const float* __restrict__ Wv) {
    __shared__ float tile[32][33];
    int n0 = blockIdx.x * 32;           // 0..1023 (n of concat)
    int k0 = blockIdx.y * 32;
    int tx = threadIdx.x & 31, ty = threadIdx.x >> 5;  // 32 x 8
    const float* W = (n0 < 512) ? Wk : Wv;
    int nn0 = (n0 < 512) ? n0 : (n0 - 512);
    for (int i = ty; i < 32; i += 8)
        tile[i][tx] = W[(size_t)(k0 + i) * 512 + nn0 + tx];
    __syncthreads();
    for (int i = ty; i < 32; i += 8) {
        float v = tile[tx][i];          // = W[k0+tx][nn0+i]
        g_bf[(size_t)(n0 + i) * 1024 + k0 + tx] = __float2half_rn(v);
    }
}

// ---- HMMA (mma.sync fp16, 1-term) K/V projection: kv = A @ B^T ----
// BM=128, BN=128, BK=64. 256 thr = 8 warps (4m x 2n), warp tile 32x64.
// fp16 single A/B makes a BK=64 stage only 36864 B -> 3 stages = 110592 B,
// STILL 2 CTAs/SM (unlike R6's bf16-hi/lo BK=64 which forced occ=1).
// Halves barrier/wait count vs BK=32 (16 chunks). Rows padded to 144 B.
#define AS_STRIDE_H 72                      // halves per SMEM row
#define MAT_BYTES   (128 * AS_STRIDE_H * 2) // 18432 per matrix tile
#define STG_BYTES   (2 * MAT_BYTES)         // 36864 per stage (A, B)
#define NSTAGE      3
#define GEMM_SMEM   (NSTAGE * STG_BYTES)    // 110592
#define NCHUNK      16

__global__ __launch_bounds__(256, 2) void kv_mma_kernel() {
    extern __shared__ char smem[];
    const uint32_t sbase = smem_u32(smem);
    const int t = threadIdx.x;
    const int wid = t >> 5, lane = t & 31;
    const int ntile = blockIdx.x;            // 0..7
    const int mtile = blockIdx.y;            // 0..515
    const size_t arow0 = (size_t)mtile * 128;
    const int    brow0 = ntile * 128;

    // global load assignment: row r_ld, 4 consecutive 16B segs (of 8/row)
    const int r_ld = t >> 1;
    const int sg4  = (t & 1) * 4;
    const __half* gA = g_af + (arow0 + r_ld) * 1024 + sg4 * 8;
    const __half* gB = g_bf + (size_t)(brow0 + r_ld) * 1024 + sg4 * 8;
    const uint32_t sAdst = sbase + r_ld * 144 + sg4 * 16;

    #define LOAD_CHUNK(chunk, stg_) do {                                       \
        uint32_t sb_ = sAdst + (stg_) * STG_BYTES;                             \
        int ko_ = (chunk) * 64;                                                \
        cp_async16(sb_,                  gA + ko_);                            \
        cp_async16(sb_ + 16,             gA + ko_ + 8);                        \
        cp_async16(sb_ + 32,             gA + ko_ + 16);                       \
        cp_async16(sb_ + 48,             gA + ko_ + 24);                       \
        cp_async16(sb_ + MAT_BYTES,      gB + ko_);                            \
        cp_async16(sb_ + MAT_BYTES + 16, gB + ko_ + 8);                        \
        cp_async16(sb_ + MAT_BYTES + 32, gB + ko_ + 16);                       \
        cp_async16(sb_ + MAT_BYTES + 48, gB + ko_ + 24);                       \
    } while (0)

    // warp tile: wm in {0,32,64,96}, wn in {0,64}
    const int wm = (wid & 3) * 32;
    const int wn = (wid >> 2) * 64;

    const int a_off_h = (wm + (lane & 15)) * AS_STRIDE_H + (lane >> 4) * 8;
    const int b_off_h = (wn + (lane & 7) + ((lane >> 3) & 1) * 8) * AS_STRIDE_H
                        + (lane >> 4) * 8;

    float acc[2][8][4];
    #pragma unroll
    for (int i = 0; i < 2; i++)
        #pragma unroll
        for (int j = 0; j < 8; j++)
            #pragma unroll
            for (int c = 0; c < 4; c++) acc[i][j][c] = 0.f;

    LOAD_CHUNK(0, 0); CP_COMMIT();
    LOAD_CHUNK(1, 1); CP_COMMIT();

    int st = 0;  // stage of current chunk
    for (int chunk = 0; chunk < NCHUNK; chunk++) {
        // pending groups at loop top: 2 (steady), 1 at last iter
        if (chunk < NCHUNK - 1) { CP_WAIT(1); } else { CP_WAIT(0); }
        __syncthreads();   // WAR: stage (st+2)%3 was consumed at chunk-1
        if (chunk + 2 < NCHUNK) {
            int stn = st + 2; if (stn >= NSTAGE) stn -= NSTAGE;
            LOAD_CHUNK(chunk + 2, stn);
            CP_COMMIT();
        }

        const uint32_t stg = sbase + st * STG_BYTES;
        #pragma unroll
        for (int ks = 0; ks < 4; ks++) {
            uint32_t a[2][4];
            #pragma unroll
            for (int mi = 0; mi < 2; mi++) {
                uint32_t ao = stg + (a_off_h + mi * 16 * AS_STRIDE_H + ks * 16) * 2;
                ldsm_x4(a[mi], ao);
            }
            #pragma unroll
            for (int nip = 0; nip < 4; nip++) {
                uint32_t bb[4];
                uint32_t bo = stg + MAT_BYTES
                            + (b_off_h + nip * 16 * AS_STRIDE_H + ks * 16) * 2;
                ldsm_x4(bb, bo);
                #pragma unroll
                for (int mi = 0; mi < 2; mi++) {
                    mma16816h(acc[mi][nip * 2],     a[mi], bb[0], bb[2]);
                    mma16816h(acc[mi][nip * 2 + 1], a[mi], bb[1], bb[3]);
                }
            }
        }
        if (++st == NSTAGE) st = 0;
    }

    // epilogue: write kv as single fp16
    const int col0 = ntile * 128 + wn + (lane & 3) * 2;
    #pragma unroll
    for (int mi = 0; mi < 2; mi++) {
        size_t row = arow0 + wm + mi * 16 + (lane >> 2);
        #pragma unroll
        for (int ni = 0; ni < 8; ni++) {
            size_t o0 = row * 1024 + col0 + ni * 8;
            size_t o1 = (row + 8) * 1024 + col0 + ni * 8;
            *(__half2*)(g_kvf + o0) = __floats2half2_rn(acc[mi][ni][0], acc[mi][ni][1]);
            *(__half2*)(g_kvf + o1) = __floats2half2_rn(acc[mi][ni][2], acc[mi][ni][3]);
        }
    }
}

// ---- generic small sgemm (mode 0: Q proj, mode 1: out proj) ----
__global__ __launch_bounds__(256) void sgemm_kernel(const float* __restrict__ Bmat,
                                                    float* __restrict__ Cext,
                                                    int M, int N, int K,
                                                    int lda, int ldb, int ldc,
                                                    float alpha, int mode) {
    const float* A = (mode == 0) ? g_lat_ln : g_attnout;
    float* C = (mode == 0) ? g_qmat : Cext;
    __shared__ float As[16][65];
    __shared__ float Bs[16][65];
    int t = threadIdx.x;
    int tx = t & 15, ty = t >> 4;
    int n0 = blockIdx.x * 64;
    int m0 = blockIdx.y * 64;
    float acc[4][4] = {};
    for (int k0 = 0; k0 < K; k0 += 16) {
        #pragma unroll
        for (int l = 0; l < 4; l++) {
            int idx = t + l * 256;
            int row = idx >> 4, kk = idx & 15;
            As[kk][row] = A[(size_t)(m0 + row) * lda + k0 + kk];
        }
        #pragma unroll
        for (int l = 0; l < 4; l++) {
            int idx = t + l * 256;
            int kk = idx >> 6, col = idx & 63;
            Bs[kk][col] = Bmat[(size_t)(k0 + kk) * ldb + n0 + col];
        }
        __syncthreads();
        #pragma unroll
        for (int kk = 0; kk < 16; kk++) {
            float a[4], bb[4];
            #pragma unroll
            for (int i = 0; i < 4; i++) a[i]  = As[kk][ty * 4 + i];
            #pragma unroll
            for (int j = 0; j < 4; j++) bb[j] = Bs[kk][tx * 4 + j];
            #pragma unroll
            for (int i = 0; i < 4; i++)
                #pragma unroll
                for (int j = 0; j < 4; j++)
                    acc[i][j] = fmaf(a[i], bb[j], acc[i][j]);
        }
        __syncthreads();
    }
    #pragma unroll
    for (int i = 0; i < 4; i++)
        #pragma unroll
        for (int j = 0; j < 4; j++)
            C[(size_t)(m0 + ty * 4 + i) * ldc + n0 + tx * 4 + j] = alpha * acc[i][j];
}

// ---- split-KV flash attention, fp16 HMMA ----
// Q split fp16 hi/lo (exact to 2^-22); K,V single fp16; P split fp16 hi/lo.
#define ATT_QSTR 72
#define ATT_KSTR 72
#define ATT_PSTR 40
#define ATT_SSTR 40
#define AOFF_QH 0
#define AOFF_QL 9216
#define AOFF_K  18432
#define AOFF_V  23040
#define AOFF_SP 27648
#define AOFF_PH 37888
#define AOFF_PL 43008
#define AOFF_M  48128
#define AOFF_L  48384
#define AOFF_AL 48640
#define AOFF_MN 48896
#define AOFF_VD 49152
#define ATT_SMEM 49280

__global__ __launch_bounds__(256) void attn_mma_kernel(const void* __restrict__ mask_raw) {
    extern __shared__ char sm[];
    const uint32_t sb = smem_u32(sm);
    const int split = blockIdx.x, h = blockIdx.y, b = blockIdx.z;
    const int t = threadIdx.x, wid = t >> 5, lane = t & 31;
    const unsigned char* mask8 = (const unsigned char*)mask_raw;
    const int*           mask32 = (const int*)mask_raw;
    const int is_byte = g_mask_is_byte;

    float* mf  = (float*)(sm + AOFF_M);
    float* lf  = (float*)(sm + AOFF_L);
    float* alf = (float*)(sm + AOFF_AL);
    float* mnf = (float*)(sm + AOFF_MN);
    float* vdf = (float*)(sm + AOFF_VD);

    // prologue: load+split Q slice (64q x 64d) to Qh/Ql (fp16 hi/lo)
    {
        int q = t >> 2, dg = (t & 3) * 16;
        const float4* src = (const float4*)(g_qmat + ((size_t)(b * NLAT + q)) * INNER
                                            + h * DHD + dg);
        __half2* qh = (__half2*)(sm + AOFF_QH + (q * ATT_QSTR + dg) * 2);
        __half2* ql = (__half2*)(sm + AOFF_QL + (q * ATT_QSTR + dg) * 2);
        #pragma unroll
        for (int i = 0; i < 4; i++) {
            float4 v = src[i];
            __half2 h01 = __floats2half2_rn(v.x, v.y);
            __half2 h23 = __floats2half2_rn(v.z, v.w);
            __half2 l01 = __floats2half2_rn(v.x - __half2float(__low2half(h01)),
                                            v.y - __half2float(__high2half(h01)));
            __half2 l23 = __floats2half2_rn(v.z - __half2float(__low2half(h23)),
                                            v.w - __half2float(__high2half(h23)));
            qh[i * 2] = h01; qh[i * 2 + 1] = h23;
            ql[i * 2] = l01; ql[i * 2 + 1] = l23;
        }
    }
    if (t < 64) { mf[t] = -1e30f; lf[t] = 0.f; }

    float acc[4][4];
    #pragma unroll
    for (int i = 0; i < 4; i++)
        #pragma unroll
        for (int j = 0; j < 4; j++) acc[i][j] = 0.f;

    const int t0 = split * TPS;
    int tcnt = NTILES - t0;
    if (tcnt > TPS) tcnt = TPS;
    if (tcnt < 0) tcnt = 0;
    __syncthreads();

    for (int it = 0; it < tcnt; it++) {
        const int j0 = (t0 + it) * JT;
        // phase 1: K/V fp16 tiles: 32 rows x 8 segs, 1 seg/thread per array
        {
            int row = t >> 3;              // 0..31
            int seg = (t & 7) * 8;         // halves
            const __half* src = g_kvf + ((size_t)b * KVLEN + j0 + row) * 1024;
            uint32_t doff = (uint32_t)(row * ATT_KSTR + seg) * 2;
            *(uint4*)(sm + AOFF_K + doff) = *(const uint4*)(src + h * DHD + seg);
            *(uint4*)(sm + AOFF_V + doff) = *(const uint4*)(src + 512 + h * DHD + seg);
        }
        if (t < JT) {
            int row = j0 + t;
            bool valid;
            if (row >= FF) valid = true;
            else {
                int mv = is_byte ? (int)mask8[b * FF + row] : mask32[b * FF + row];
                valid = (mv == 0);
            }
            vdf[t] = valid ? 1.f : 0.f;
        }
        __syncthreads();

        // phase 2: S = Q K^T (2-term fp16), write SP[q][j]
        {
            const int wq = (wid & 3) * 16, wj = (wid >> 2) * 16;
            float c0[4] = {0.f, 0.f, 0.f, 0.f};
            float c1[4] = {0.f, 0.f, 0.f, 0.f};
            #pragma unroll
            for (int ks = 0; ks < 4; ks++) {
                uint32_t aqh[4], aql[4], bk[4];
                uint32_t aoff = ((wq + (lane & 15)) * ATT_QSTR + ks * 16
                                 + (lane >> 4) * 8) * 2;
                ldsm_x4(aqh, sb + AOFF_QH + aoff);
                ldsm_x4(aql, sb + AOFF_QL + aoff);
                uint32_t boff = ((wj + (lane & 7) + ((lane >> 3) & 1) * 8) * ATT_KSTR
                                 + ks * 16 + (lane >> 4) * 8) * 2;
                ldsm_x4(bk, sb + AOFF_K + boff);
                mma16816h(c0, aqh, bk[0], bk[2]);
                mma16816h(c0, aql, bk[0], bk[2]);
                mma16816h(c1, aqh, bk[1], bk[3]);
                mma16816h(c1, aql, bk[1], bk[3]);
            }
            float* sp = (float*)(sm + AOFF_SP);
            int r = lane >> 2, cc = (lane & 3) * 2;
            *(float2*)&sp[(wq + r) * ATT_SSTR + wj + cc]      = make_float2(c0[0], c0[1]);
            *(float2*)&sp[(wq + r + 8) * ATT_SSTR + wj + cc]  = make_float2(c0[2], c0[3]);
            *(float2*)&sp[(wq + r) * ATT_SSTR + wj + 8 + cc]  = make_float2(c1[0], c1[1]);
            *(float2*)&sp[(wq + r + 8) * ATT_SSTR + wj + 8 + cc] = make_float2(c1[2], c1[3]);
        }
        __syncthreads();

        // phase 3: masked row max -> mnew, alpha
        if (t < 64) {
            const float* sp = (const float*)(sm + AOFF_SP) + t * ATT_SSTR;
            float mx = -1e30f;
            #pragma unroll
            for (int j = 0; j < JT; j++)
                mx = fmaxf(mx, (vdf[j] != 0.f) ? sp[j] : -1e30f);
            float mold = mf[t];
            float mnew = fmaxf(mold, mx);
            mnf[t] = mnew;
            alf[t] = __expf(mold - mnew);
            mf[t]  = mnew;
        }
        __syncthreads();

        // phase 4: P = exp(S - mnew) masked; split to Ph/Pl (fp16); acc *= alpha
        {
            int q = t >> 2, jg = (t & 3) * 8;
            float* sp = (float*)(sm + AOFF_SP) + q * ATT_SSTR + jg;
            float mn = mnf[q];
            __half2* ph = (__half2*)(sm + AOFF_PH + (q * ATT_PSTR + jg) * 2);
            __half2* pl = (__half2*)(sm + AOFF_PL + (q * ATT_PSTR + jg) * 2);
            #pragma unroll
            for (int i = 0; i < 8; i += 2) {
                float e0 = (vdf[jg + i]     != 0.f) ? __expf(sp[i]     - mn) : 0.f;
                float e1 = (vdf[jg + i + 1] != 0.f) ? __expf(sp[i + 1] - mn) : 0.f;
                sp[i] = e0; sp[i + 1] = e1;
                __half2 hh = __floats2half2_rn(e0, e1);
                __half2 ll = __floats2half2_rn(e0 - __half2float(__low2half(hh)),
                                               e1 - __half2float(__high2half(hh)));
                ph[i >> 1] = hh; pl[i >> 1] = ll;
            }
            const int wq = (wid & 3) * 16;
            float a1 = alf[wq + (lane >> 2)];
            float a2 = alf[wq + (lane >> 2) + 8];
            #pragma unroll
            for (int ni = 0; ni < 4; ni++) {
                acc[ni][0] *= a1; acc[ni][1] *= a1;
                acc[ni][2] *= a2; acc[ni][3] *= a2;
            }
        }
        __syncthreads();

        // phase 5: l update + O += P V (2-term fp16)
        if (t < 64) {
            const float* sp = (const float*)(sm + AOFF_SP) + t * ATT_SSTR;
            float s = 0.f;
            #pragma unroll
            for (int j = 0; j < JT; j++) s += sp[j];
            lf[t] = lf[t] * alf[t] + s;
        }
        {
            const int wq = (wid & 3) * 16, wd = (wid >> 2) * 32;
            #pragma unroll
            for (int ks = 0; ks < 2; ks++) {
                uint32_t aph[4], apl[4], bv0[4], bv1[4];
                uint32_t aoff = ((wq + (lane & 15)) * ATT_PSTR + ks * 16
                                 + (lane >> 4) * 8) * 2;
                ldsm_x4(aph, sb + AOFF_PH + aoff);
                ldsm_x4(apl, sb + AOFF_PL + aoff);
                uint32_t vrow = ks * 16 + (lane & 15);
                uint32_t v0 = (vrow * ATT_KSTR + wd + (lane >> 4) * 8) * 2;
                uint32_t v1 = (vrow * ATT_KSTR + wd + 16 + (lane >> 4) * 8) * 2;
                ldsm_x4_trans(bv0, sb + AOFF_V + v0);
                ldsm_x4_trans(bv1, sb + AOFF_V + v1);
                mma16816h(acc[0], aph, bv0[0], bv0[1]);
                mma16816h(acc[0], apl, bv0[0], bv0[1]);
                mma16816h(acc[1], aph, bv0[2], bv0[3]);
                mma16816h(acc[1], apl, bv0[2], bv0[3]);
                mma16816h(acc[2], aph, bv1[0], bv1[1]);
                mma16816h(acc[2], apl, bv1[0], bv1[1]);
                mma16816h(acc[3], aph, bv1[2], bv1[3]);
                mma16816h(acc[3], apl, bv1[2], bv1[3]);
            }
        }
        __syncthreads();
    }

    // epilogue: write partials
    {
        const int wq = (wid & 3) * 16, wd = (wid >> 2) * 32;
        size_t pbase = ((((size_t)b * HH + h) * NSPLIT + split) * NLAT) * (size_t)DHD;
        int r = lane >> 2, cc = (lane & 3) * 2;
        #pragma unroll
        for (int ni = 0; ni < 4; ni++) {
            float* d0 = g_pacc + pbase + (size_t)(wq + r) * DHD + wd + ni * 8 + cc;
            float* d1 = g_pacc + pbase + (size_t)(wq + r + 8) * DHD + wd + ni * 8 + cc;
            *(float2*)d0 = make_float2(acc[ni][0], acc[ni][1]);
            *(float2*)d1 = make_float2(acc[ni][2], acc[ni][3]);
        }
    }
    if (t < 64) {
        size_t sbi = (((size_t)b * HH + h) * NSPLIT + split) * NLAT + t;
        g_pm[sbi] = mf[t];
        g_pl[sbi] = lf[t];
    }
}

// ---- pass B: combine split partials -> attn output (b, q, h*64+d) ----
__global__ __launch_bounds__(64) void attn_combine_kernel() {
    int q = blockIdx.x, h = blockIdx.y, b = blockIdx.z;
    int d = threadIdx.x;
    size_t sb = (((size_t)b * HH + h) * NSPLIT) * NLAT + q;
    float mg = -1e30f;
    #pragma unroll
    for (int s = 0; s < NSPLIT; s++) mg = fmaxf(mg, g_pm[sb + (size_t)s * NLAT]);
    float denom = 0.f, a = 0.f;
    #pragma unroll
    for (int s = 0; s < NSPLIT; s++) {
        float w = __expf(g_pm[sb + (size_t)s * NLAT] - mg);
        denom += g_pl[sb + (size_t)s * NLAT] * w;
        a += g_pacc[((((size_t)b * HH + h) * NSPLIT + s) * NLAT + q) * DHD + d] * w;
    }
    g_attnout[((size_t)b * NLAT + q) * INNER + h * DHD + d] = a / denom;
}

extern "C" void kernel_launch(void* const* d_in, const int* in_sizes, int n_in,
                              void* d_out, int out_size) {
    const float* x    = (const float*)d_in[0];
    const float* lat  = (const float*)d_in[1];
    const void*  mask = d_in[2];
    const float* gate = (const float*)d_in[3];
    const float* gm   = (const float*)d_in[4];
    const float* bm   = (const float*)d_in[5];
    const float* gl   = (const float*)d_in[6];
    const float* bl   = (const float*)d_in[7];
    const float* Wq   = (const float*)d_in[8];
    const float* Wk   = (const float*)d_in[9];
    const float* Wv   = (const float*)d_in[10];
    const float* Wout = (const float*)d_in[11];
    float* out = (float*)d_out;

    cudaFuncSetAttribute(kv_mma_kernel,
                         cudaFuncAttributeMaxDynamicSharedMemorySize, GEMM_SMEM);
    cudaFuncSetAttribute(attn_mma_kernel,
                         cudaFuncAttributeMaxDynamicSharedMemorySize, ATT_SMEM);

    // Launch order puts kv_mma_kernel 4th (the slot ncu's -s/-c window captures).
    ln_lat_kernel<<<BB * NLAT, 256>>>(lat, gl, bl, (const unsigned int*)mask);
    prep_a_kernel<<<MROWS / 8, 256>>>(x, gm, bm, gate);
    prep_w_kernel<<<dim3(32, 32), 256>>>(Wk, Wv);
    kv_mma_kernel<<<dim3(8, 516), 256, GEMM_SMEM>>>();
    // Q = lat_ln @ Wq, scaled by DIM_HEAD^-0.5 = 0.125
    sgemm_kernel<<<dim3(INNER / 64, (BB * NLAT) / 64), 256>>>(
        Wq, nullptr, BB * NLAT, INNER, DD, DD, INNER, INNER, 0.125f, 0);
    attn_mma_kernel<<<dim3(NSPLIT, HH, BB), 256, ATT_SMEM>>>(mask);
    attn_combine_kernel<<<dim3(NLAT, HH, BB), 64>>>();
    sgemm_kernel<<<dim3(DD / 64, (BB * NLAT) / 64), 256>>>(
        Wout, out, BB * NLAT, DD, INNER, INNER, DD, DD, 1.0f, 1);
}

// round 13
// speedup vs baseline: 1.3947x; 1.0539x over previous
#include <cuda_runtime.h>
#include <cuda_bf16.h>
#include <cuda_fp16.h>
#include <cstdint>

// Problem dims (fixed by the dataset)
#define BB     8
#define FF     8192
#define NLAT   64
#define DD     1024
#define HH     8
#define DHD    64
#define INNER  512
#define KVLEN  (FF + NLAT)          // 8256
#define MROWS  (BB * KVLEN)         // 66048
#define NSPLIT 16
#define JT     32                    // kv tile in attention
#define NTILES (KVLEN / JT)          // 258
#define TPS    ((NTILES + NSPLIT - 1) / NSPLIT)  // 17
#define LN_EPS 1e-5f

// ---------------- family-safe PTX helpers (sm_80-era; no 'a'-features) ------
__device__ __forceinline__ uint32_t smem_u32(const void* p) {
    uint32_t a;
    asm("{ .reg .u64 t; cvta.to.shared.u64 t, %1; cvt.u32.u64 %0, t; }" : "=r"(a) : "l"(p));
    return a;
}
__device__ __forceinline__ void cp_async16(uint32_t dst, const void* src) {
    asm volatile("cp.async.cg.shared.global [%0], [%1], 16;" :: "r"(dst), "l"(src));
}
#define CP_COMMIT() asm volatile("cp.async.commit_group;" ::: "memory")
#define CP_WAIT(n)  asm volatile("cp.async.wait_group %0;" :: "n"(n) : "memory")

__device__ __forceinline__ void ldsm_x4(uint32_t* r, uint32_t addr) {
    asm volatile("ldmatrix.sync.aligned.m8n8.x4.shared.b16 {%0,%1,%2,%3}, [%4];"
        : "=r"(r[0]), "=r"(r[1]), "=r"(r[2]), "=r"(r[3]) : "r"(addr));
}
__device__ __forceinline__ void ldsm_x4_trans(uint32_t* r, uint32_t addr) {
    asm volatile("ldmatrix.sync.aligned.m8n8.x4.trans.shared.b16 {%0,%1,%2,%3}, [%4];"
        : "=r"(r[0]), "=r"(r[1]), "=r"(r[2]), "=r"(r[3]) : "r"(addr));
}
// fp16 mma
__device__ __forceinline__ void mma16816h(float* c, const uint32_t* a,
                                          uint32_t b0, uint32_t b1) {
    asm volatile(
        "mma.sync.aligned.m16n8k16.row.col.f32.f16.f16.f32 "
        "{%0,%1,%2,%3}, {%4,%5,%6,%7}, {%8,%9}, {%0,%1,%2,%3};"
        : "+f"(c[0]), "+f"(c[1]), "+f"(c[2]), "+f"(c[3])
        : "r"(a[0]), "r"(a[1]), "r"(a[2]), "r"(a[3]), "r"(b0), "r"(b1));
}

// -------- scratch (device globals; no allocations allowed) --------
__device__ float          g_lat_ln[BB * NLAT * DD];                       // 2 MB
__device__ __half         g_af[(size_t)MROWS * DD];                       // 135 MB (A fp16)
__device__ __half         g_bf[1024 * 1024];                              // 2 MB  [n][k] fp16
__device__ __half         g_kvf[(size_t)MROWS * 1024];                    // 135 MB (cols 0-511 K, 512-1023 V)
__device__ float          g_qmat[BB * NLAT * INNER];                      // 1 MB
__device__ float          g_attnout[BB * NLAT * INNER];                   // 1 MB
__device__ float          g_pacc[(size_t)BB * HH * NSPLIT * NLAT * DHD];  // 16.8 MB
__device__ float          g_pm[BB * HH * NSPLIT * NLAT];
__device__ float          g_pl[BB * HH * NSPLIT * NLAT];
__device__ int            g_mask_is_byte;

// ---- LayerNorm of latents + (block 0) mask dtype detection ----
__global__ __launch_bounds__(256) void ln_lat_kernel(const float* __restrict__ lat,
                                                     const float* __restrict__ gamma,
                                                     const float* __restrict__ beta,
                                                     const unsigned int* __restrict__ mask_w) {
    int row = blockIdx.x;
    int t = threadIdx.x;
    if (row == 0 && t == 0) {
        unsigned int acc = 0;
        #pragma unroll
        for (int i = 0; i < 64; i++) acc |= mask_w[i];
        g_mask_is_byte = (acc > 1u) ? 1 : 0;
    }
    float4 v = ((const float4*)(lat + (size_t)row * DD))[t];
    __shared__ float rs[256], rq[256];
    rs[t] = v.x + v.y + v.z + v.w;
    rq[t] = v.x*v.x + v.y*v.y + v.z*v.z + v.w*v.w;
    __syncthreads();
    for (int off = 128; off > 0; off >>= 1) {
        if (t < off) { rs[t] += rs[t + off]; rq[t] += rq[t + off]; }
        __syncthreads();
    }
    float mu   = rs[0] * (1.f / DD);
    float var  = rq[0] * (1.f / DD) - mu * mu;
    float rstd = rsqrtf(var + LN_EPS);
    float4 gv = ((const float4*)gamma)[t];
    float4 bv = ((const float4*)beta)[t];
    float4 o;
    o.x = (v.x - mu) * rstd * gv.x + bv.x;
    o.y = (v.y - mu) * rstd * gv.y + bv.y;
    o.z = (v.z - mu) * rstd * gv.z + bv.z;
    o.w = (v.w - mu) * rstd * gv.w + bv.w;
    ((float4*)(g_lat_ln + (size_t)row * DD))[t] = o;
}

// ---- fused LN + fp16 store of A: one row per warp, shuffle reduction ----
__global__ __launch_bounds__(256) void prep_a_kernel(const float* __restrict__ x,
                                                     const float* __restrict__ gm_,
                                                     const float* __restrict__ bm_,
                                                     const float* __restrict__ gate_p) {
    int wid = threadIdx.x >> 5, lane = threadIdx.x & 31;
    int row = blockIdx.x * 8 + wid;       // 0..MROWS-1 (grid = MROWS/8)
    int b = row / KVLEN;
    int r = row - b * KVLEN;
    float4 v[8];
    const float4* src;
    if (r < FF) src = (const float4*)(x + ((size_t)b * FF + r) * DD);
    else        src = (const float4*)(g_lat_ln + ((size_t)b * NLAT + (r - FF)) * DD);
    #pragma unroll
    for (int i = 0; i < 8; i++) v[i] = src[lane + 32 * i];

    if (r < FF) {
        float s = 0.f, q = 0.f;
        #pragma unroll
        for (int i = 0; i < 8; i++) {
            s += v[i].x + v[i].y + v[i].z + v[i].w;
            q += v[i].x*v[i].x + v[i].y*v[i].y + v[i].z*v[i].z + v[i].w*v[i].w;
        }
        #pragma unroll
        for (int off = 16; off > 0; off >>= 1) {
            s += __shfl_xor_sync(0xffffffffu, s, off);
            q += __shfl_xor_sync(0xffffffffu, q, off);
        }
        float mu   = s * (1.f / DD);
        float var  = q * (1.f / DD) - mu * mu;
        float rstd = rsqrtf(var + LN_EPS);
        #pragma unroll
        for (int i = 0; i < 8; i++) {
            float4 gv = ((const float4*)gm_)[lane + 32 * i];
            float4 bv = ((const float4*)bm_)[lane + 32 * i];
            v[i].x = (v[i].x - mu) * rstd * gv.x + bv.x;
            v[i].y = (v[i].y - mu) * rstd * gv.y + bv.y;
            v[i].z = (v[i].z - mu) * rstd * gv.z + bv.z;
            v[i].w = (v[i].w - mu) * rstd * gv.w + bv.w;
        }
    } else {
        float gate = gate_p[0];
        #pragma unroll
        for (int i = 0; i < 8; i++) {
            v[i].x *= gate; v[i].y *= gate; v[i].z *= gate; v[i].w *= gate;
        }
    }
    uint2* dst = (uint2*)(g_af + (size_t)row * DD);
    #pragma unroll
    for (int i = 0; i < 8; i++) {
        __half2 h01 = __floats2half2_rn(v[i].x, v[i].y);
        __half2 h23 = __floats2half2_rn(v[i].z, v[i].w);
        uint2 u;
        u.x = *(uint32_t*)&h01;
        u.y = *(uint32_t*)&h23;
        dst[lane + 32 * i] = u;
    }
}

// ---- transpose [Wk|Wv] (k-major [1024][512] each) into B[n][k] fp16 ----
__global__ __launch_bounds__(256) void prep_w_kernel(const float* __restrict__ Wk,
                                                     const float* __restrict__ Wv) {
    __shared__ float tile[32][33];
    int n0 = blockIdx.x * 32;           // 0..1023 (n of concat)
    int k0 = blockIdx.y * 32;
    int tx = threadIdx.x & 31, ty = threadIdx.x >> 5;  // 32 x 8
    const float* W = (n0 < 512) ? Wk : Wv;
    int nn0 = (n0 < 512) ? n0 : (n0 - 512);
    for (int i = ty; i < 32; i += 8)
        tile[i][tx] = W[(size_t)(k0 + i) * 512 + nn0 + tx];
    __syncthreads();
    for (int i = ty; i < 32; i += 8) {
        float v = tile[tx][i];          // = W[k0+tx][nn0+i]
        g_bf[(size_t)(n0 + i) * 1024 + k0 + tx] = __float2half_rn(v);
    }
}

// ---- HMMA (mma.sync fp16, 1-term) K/V projection: kv = A @ B^T ----
// R11-proven config: BM=128, BN=128, BK=32, 256 thr = 8 warps (4m x 2n),
// warp tile 32x64, ~108 regs, 2 CTAs/SM, 4-stage pipeline, prefetch dist 3.
// (BK=64 tried twice — R6: occupancy loss, R12: prefetch-distance loss — both
//  regressed. This shape is the measured local optimum: 547 us, tensor 42%.)
#define AS_STRIDE_H 40                      // halves per SMEM row
#define MAT_BYTES   (128 * AS_STRIDE_H * 2) // 10240 per matrix tile
#define STG_BYTES   (2 * MAT_BYTES)         // 20480 per stage (A, B)
#define NSTAGE      4
#define GEMM_SMEM   (NSTAGE * STG_BYTES)    // 81920
#define NCHUNK      32

__global__ __launch_bounds__(256, 2) void kv_mma_kernel() {
    extern __shared__ char smem[];
    const uint32_t sbase = smem_u32(smem);
    const int t = threadIdx.x;
    const int wid = t >> 5, lane = t & 31;
    const int ntile = blockIdx.x;            // 0..7
    const int mtile = blockIdx.y;            // 0..515
    const size_t arow0 = (size_t)mtile * 128;
    const int    brow0 = ntile * 128;

    // global load assignment: row r_ld, two consecutive 16B segs
    const int r_ld = t >> 1;
    const int seg0 = (t & 1) * 2;            // 0 or 2 (of 4 segs/row)
    const __half* gA = g_af + (arow0 + r_ld) * 1024 + seg0 * 8;
    const __half* gB = g_bf + (size_t)(brow0 + r_ld) * 1024 + seg0 * 8;
    const uint32_t sAdst = sbase + r_ld * 80 + seg0 * 16;

    #define LOAD_CHUNK(chunk, stg_) do {                                       \
        uint32_t sb_ = sAdst + (stg_) * STG_BYTES;                             \
        int ko_ = (chunk) * 32;                                                \
        cp_async16(sb_,                  gA + ko_);                            \
        cp_async16(sb_ + 16,             gA + ko_ + 8);                        \
        cp_async16(sb_ + MAT_BYTES,      gB + ko_);                            \
        cp_async16(sb_ + MAT_BYTES + 16, gB + ko_ + 8);                        \
    } while (0)

    // warp tile: wm in {0,32,64,96}, wn in {0,64}
    const int wm = (wid & 3) * 32;
    const int wn = (wid >> 2) * 64;

    const int a_off_h = (wm + (lane & 15)) * AS_STRIDE_H + (lane >> 4) * 8;
    const int b_off_h = (wn + (lane & 7) + ((lane >> 3) & 1) * 8) * AS_STRIDE_H
                        + (lane >> 4) * 8;

    float acc[2][8][4];
    #pragma unroll
    for (int i = 0; i < 2; i++)
        #pragma unroll
        for (int j = 0; j < 8; j++)
            #pragma unroll
            for (int c = 0; c < 4; c++) acc[i][j][c] = 0.f;

    LOAD_CHUNK(0, 0); CP_COMMIT();
    LOAD_CHUNK(1, 1); CP_COMMIT();
    LOAD_CHUNK(2, 2); CP_COMMIT();

    int st = 0;  // stage of current chunk
    for (int chunk = 0; chunk < NCHUNK; chunk++) {
        if (chunk < NCHUNK - 2)       { CP_WAIT(2); }
        else if (chunk == NCHUNK - 2) { CP_WAIT(1); }
        else                          { CP_WAIT(0); }
        __syncthreads();   // also protects WAR on the stage being refilled
        if (chunk + 3 < NCHUNK) {
            int stn = st + 3; if (stn >= NSTAGE) stn -= NSTAGE;
            LOAD_CHUNK(chunk + 3, stn);
            CP_COMMIT();
        }

        const uint32_t stg = sbase + st * STG_BYTES;
        #pragma unroll
        for (int ks = 0; ks < 2; ks++) {
            uint32_t a[2][4];
            #pragma unroll
            for (int mi = 0; mi < 2; mi++) {
                uint32_t ao = stg + (a_off_h + mi * 16 * AS_STRIDE_H + ks * 16) * 2;
                ldsm_x4(a[mi], ao);
            }
            #pragma unroll
            for (int nip = 0; nip < 4; nip++) {
                uint32_t bb[4];
                uint32_t bo = stg + MAT_BYTES
                            + (b_off_h + nip * 16 * AS_STRIDE_H + ks * 16) * 2;
                ldsm_x4(bb, bo);
                #pragma unroll
                for (int mi = 0; mi < 2; mi++) {
                    mma16816h(acc[mi][nip * 2],     a[mi], bb[0], bb[2]);
                    mma16816h(acc[mi][nip * 2 + 1], a[mi], bb[1], bb[3]);
                }
            }
        }
        if (++st == NSTAGE) st = 0;
    }

    // epilogue: write kv as single fp16
    const int col0 = ntile * 128 + wn + (lane & 3) * 2;
    #pragma unroll
    for (int mi = 0; mi < 2; mi++) {
        size_t row = arow0 + wm + mi * 16 + (lane >> 2);
        #pragma unroll
        for (int ni = 0; ni < 8; ni++) {
            size_t o0 = row * 1024 + col0 + ni * 8;
            size_t o1 = (row + 8) * 1024 + col0 + ni * 8;
            *(__half2*)(g_kvf + o0) = __floats2half2_rn(acc[mi][ni][0], acc[mi][ni][1]);
            *(__half2*)(g_kvf + o1) = __floats2half2_rn(acc[mi][ni][2], acc[mi][ni][3]);
        }
    }
}

// ---- generic small sgemm (mode 0: Q proj, mode 1: out proj) ----
__global__ __launch_bounds__(256) void sgemm_kernel(const float* __restrict__ Bmat,
                                                    float* __restrict__ Cext,
                                                    int M, int N, int K,
                                                    int lda, int ldb, int ldc,
                                                    float alpha, int mode) {
    const float* A = (mode == 0) ? g_lat_ln : g_attnout;
    float* C = (mode == 0) ? g_qmat : Cext;
    __shared__ float As[16][65];
    __shared__ float Bs[16][65];
    int t = threadIdx.x;
    int tx = t & 15, ty = t >> 4;
    int n0 = blockIdx.x * 64;
    int m0 = blockIdx.y * 64;
    float acc[4][4] = {};
    for (int k0 = 0; k0 < K; k0 += 16) {
        #pragma unroll
        for (int l = 0; l < 4; l++) {
            int idx = t + l * 256;
            int row = idx >> 4, kk = idx & 15;
            As[kk][row] = A[(size_t)(m0 + row) * lda + k0 + kk];
        }
        #pragma unroll
        for (int l = 0; l < 4; l++) {
            int idx = t + l * 256;
            int kk = idx >> 6, col = idx & 63;
            Bs[kk][col] = Bmat[(size_t)(k0 + kk) * ldb + n0 + col];
        }
        __syncthreads();
        #pragma unroll
        for (int kk = 0; kk < 16; kk++) {
            float a[4], bb[4];
            #pragma unroll
            for (int i = 0; i < 4; i++) a[i]  = As[kk][ty * 4 + i];
            #pragma unroll
            for (int j = 0; j < 4; j++) bb[j] = Bs[kk][tx * 4 + j];
            #pragma unroll
            for (int i = 0; i < 4; i++)
                #pragma unroll
                for (int j = 0; j < 4; j++)
                    acc[i][j] = fmaf(a[i], bb[j], acc[i][j]);
        }
        __syncthreads();
    }
    #pragma unroll
    for (int i = 0; i < 4; i++)
        #pragma unroll
        for (int j = 0; j < 4; j++)
            C[(size_t)(m0 + ty * 4 + i) * ldc + n0 + tx * 4 + j] = alpha * acc[i][j];
}

// ---- split-KV flash attention, fp16 HMMA ----
// Q split fp16 hi/lo (exact to 2^-22); K,V single fp16; P split fp16 hi/lo.
#define ATT_QSTR 72
#define ATT_KSTR 72
#define ATT_PSTR 40
#define ATT_SSTR 40
#define AOFF_QH 0
#define AOFF_QL 9216
#define AOFF_K  18432
#define AOFF_V  23040
#define AOFF_SP 27648
#define AOFF_PH 37888
#define AOFF_PL 43008
#define AOFF_M  48128
#define AOFF_L  48384
#define AOFF_AL 48640
#define AOFF_MN 48896
#define AOFF_VD 49152
#define ATT_SMEM 49280

__global__ __launch_bounds__(256) void attn_mma_kernel(const void* __restrict__ mask_raw) {
    extern __shared__ char sm[];
    const uint32_t sb = smem_u32(sm);
    const int split = blockIdx.x, h = blockIdx.y, b = blockIdx.z;
    const int t = threadIdx.x, wid = t >> 5, lane = t & 31;
    const unsigned char* mask8 = (const unsigned char*)mask_raw;
    const int*           mask32 = (const int*)mask_raw;
    const int is_byte = g_mask_is_byte;

    float* mf  = (float*)(sm + AOFF_M);
    float* lf  = (float*)(sm + AOFF_L);
    float* alf = (float*)(sm + AOFF_AL);
    float* mnf = (float*)(sm + AOFF_MN);
    float* vdf = (float*)(sm + AOFF_VD);

    // prologue: load+split Q slice (64q x 64d) to Qh/Ql (fp16 hi/lo)
    {
        int q = t >> 2, dg = (t & 3) * 16;
        const float4* src = (const float4*)(g_qmat + ((size_t)(b * NLAT + q)) * INNER
                                            + h * DHD + dg);
        __half2* qh = (__half2*)(sm + AOFF_QH + (q * ATT_QSTR + dg) * 2);
        __half2* ql = (__half2*)(sm + AOFF_QL + (q * ATT_QSTR + dg) * 2);
        #pragma unroll
        for (int i = 0; i < 4; i++) {
            float4 v = src[i];
            __half2 h01 = __floats2half2_rn(v.x, v.y);
            __half2 h23 = __floats2half2_rn(v.z, v.w);
            __half2 l01 = __floats2half2_rn(v.x - __half2float(__low2half(h01)),
                                            v.y - __half2float(__high2half(h01)));
            __half2 l23 = __floats2half2_rn(v.z - __half2float(__low2half(h23)),
                                            v.w - __half2float(__high2half(h23)));
            qh[i * 2] = h01; qh[i * 2 + 1] = h23;
            ql[i * 2] = l01; ql[i * 2 + 1] = l23;
        }
    }
    if (t < 64) { mf[t] = -1e30f; lf[t] = 0.f; }

    float acc[4][4];
    #pragma unroll
    for (int i = 0; i < 4; i++)
        #pragma unroll
        for (int j = 0; j < 4; j++) acc[i][j] = 0.f;

    const int t0 = split * TPS;
    int tcnt = NTILES - t0;
    if (tcnt > TPS) tcnt = TPS;
    if (tcnt < 0) tcnt = 0;
    __syncthreads();

    for (int it = 0; it < tcnt; it++) {
        const int j0 = (t0 + it) * JT;
        // phase 1: K/V fp16 tiles: 32 rows x 8 segs, 1 seg/thread per array
        {
            int row = t >> 3;              // 0..31
            int seg = (t & 7) * 8;         // halves
            const __half* src = g_kvf + ((size_t)b * KVLEN + j0 + row) * 1024;
            uint32_t doff = (uint32_t)(row * ATT_KSTR + seg) * 2;
            *(uint4*)(sm + AOFF_K + doff) = *(const uint4*)(src + h * DHD + seg);
            *(uint4*)(sm + AOFF_V + doff) = *(const uint4*)(src + 512 + h * DHD + seg);
        }
        if (t < JT) {
            int row = j0 + t;
            bool valid;
            if (row >= FF) valid = true;
            else {
                int mv = is_byte ? (int)mask8[b * FF + row] : mask32[b * FF + row];
                valid = (mv == 0);
            }
            vdf[t] = valid ? 1.f : 0.f;
        }
        __syncthreads();

        // phase 2: S = Q K^T (2-term fp16), write SP[q][j]
        {
            const int wq = (wid & 3) * 16, wj = (wid >> 2) * 16;
            float c0[4] = {0.f, 0.f, 0.f, 0.f};
            float c1[4] = {0.f, 0.f, 0.f, 0.f};
            #pragma unroll
            for (int ks = 0; ks < 4; ks++) {
                uint32_t aqh[4], aql[4], bk[4];
                uint32_t aoff = ((wq + (lane & 15)) * ATT_QSTR + ks * 16
                                 + (lane >> 4) * 8) * 2;
                ldsm_x4(aqh, sb + AOFF_QH + aoff);
                ldsm_x4(aql, sb + AOFF_QL + aoff);
                uint32_t boff = ((wj + (lane & 7) + ((lane >> 3) & 1) * 8) * ATT_KSTR
                                 + ks * 16 + (lane >> 4) * 8) * 2;
                ldsm_x4(bk, sb + AOFF_K + boff);
                mma16816h(c0, aqh, bk[0], bk[2]);
                mma16816h(c0, aql, bk[0], bk[2]);
                mma16816h(c1, aqh, bk[1], bk[3]);
                mma16816h(c1, aql, bk[1], bk[3]);
            }
            float* sp = (float*)(sm + AOFF_SP);
            int r = lane >> 2, cc = (lane & 3) * 2;
            *(float2*)&sp[(wq + r) * ATT_SSTR + wj + cc]      = make_float2(c0[0], c0[1]);
            *(float2*)&sp[(wq + r + 8) * ATT_SSTR + wj + cc]  = make_float2(c0[2], c0[3]);
            *(float2*)&sp[(wq + r) * ATT_SSTR + wj + 8 + cc]  = make_float2(c1[0], c1[1]);
            *(float2*)&sp[(wq + r + 8) * ATT_SSTR + wj + 8 + cc] = make_float2(c1[2], c1[3]);
        }
        __syncthreads();

        // phase 3: masked row max -> mnew, alpha
        if (t < 64) {
            const float* sp = (const float*)(sm + AOFF_SP) + t * ATT_SSTR;
            float mx = -1e30f;
            #pragma unroll
            for (int j = 0; j < JT; j++)
                mx = fmaxf(mx, (vdf[j] != 0.f) ? sp[j] : -1e30f);
            float mold = mf[t];
            float mnew = fmaxf(mold, mx);
            mnf[t] = mnew;
            alf[t] = __expf(mold - mnew);
            mf[t]  = mnew;
        }
        __syncthreads();

        // phase 4: P = exp(S - mnew) masked; split to Ph/Pl (fp16); acc *= alpha
        {
            int q = t >> 2, jg = (t & 3) * 8;
            float* sp = (float*)(sm + AOFF_SP) + q * ATT_SSTR + jg;
            float mn = mnf[q];
            __half2* ph = (__half2*)(sm + AOFF_PH + (q * ATT_PSTR + jg) * 2);
            __half2* pl = (__half2*)(sm + AOFF_PL + (q * ATT_PSTR + jg) * 2);
            #pragma unroll
            for (int i = 0; i < 8; i += 2) {
                float e0 = (vdf[jg + i]     != 0.f) ? __expf(sp[i]     - mn) : 0.f;
                float e1 = (vdf[jg + i + 1] != 0.f) ? __expf(sp[i + 1] - mn) : 0.f;
                sp[i] = e0; sp[i + 1] = e1;
                __half2 hh = __floats2half2_rn(e0, e1);
                __half2 ll = __floats2half2_rn(e0 - __half2float(__low2half(hh)),
                                               e1 - __half2float(__high2half(hh)));
                ph[i >> 1] = hh; pl[i >> 1] = ll;
            }
            const int wq = (wid & 3) * 16;
            float a1 = alf[wq + (lane >> 2)];
            float a2 = alf[wq + (lane >> 2) + 8];
            #pragma unroll
            for (int ni = 0; ni < 4; ni++) {
                acc[ni][0] *= a1; acc[ni][1] *= a1;
                acc[ni][2] *= a2; acc[ni][3] *= a2;
            }
        }
        __syncthreads();

        // phase 5: l update + O += P V (2-term fp16)
        if (t < 64) {
            const float* sp = (const float*)(sm + AOFF_SP) + t * ATT_SSTR;
            float s = 0.f;
            #pragma unroll
            for (int j = 0; j < JT; j++) s += sp[j];
            lf[t] = lf[t] * alf[t] + s;
        }
        {
            const int wq = (wid & 3) * 16, wd = (wid >> 2) * 32;
            #pragma unroll
            for (int ks = 0; ks < 2; ks++) {
                uint32_t aph[4], apl[4], bv0[4], bv1[4];
                uint32_t aoff = ((wq + (lane & 15)) * ATT_PSTR + ks * 16
                                 + (lane >> 4) * 8) * 2;
                ldsm_x4(aph, sb + AOFF_PH + aoff);
                ldsm_x4(apl, sb + AOFF_PL + aoff);
                uint32_t vrow = ks * 16 + (lane & 15);
                uint32_t v0 = (vrow * ATT_KSTR + wd + (lane >> 4) * 8) * 2;
                uint32_t v1 = (vrow * ATT_KSTR + wd + 16 + (lane >> 4) * 8) * 2;
                ldsm_x4_trans(bv0, sb + AOFF_V + v0);
                ldsm_x4_trans(bv1, sb + AOFF_V + v1);
                mma16816h(acc[0], aph, bv0[0], bv0[1]);
                mma16816h(acc[0], apl, bv0[0], bv0[1]);
                mma16816h(acc[1], aph, bv0[2], bv0[3]);
                mma16816h(acc[1], apl, bv0[2], bv0[3]);
                mma16816h(acc[2], aph, bv1[0], bv1[1]);
                mma16816h(acc[2], apl, bv1[0], bv1[1]);
                mma16816h(acc[3], aph, bv1[2], bv1[3]);
                mma16816h(acc[3], apl, bv1[2], bv1[3]);
            }
        }
        __syncthreads();
    }

    // epilogue: write partials
    {
        const int wq = (wid & 3) * 16, wd = (wid >> 2) * 32;
        size_t pbase = ((((size_t)b * HH + h) * NSPLIT + split) * NLAT) * (size_t)DHD;
        int r = lane >> 2, cc = (lane & 3) * 2;
        #pragma unroll
        for (int ni = 0; ni < 4; ni++) {
            float* d0 = g_pacc + pbase + (size_t)(wq + r) * DHD + wd + ni * 8 + cc;
            float* d1 = g_pacc + pbase + (size_t)(wq + r + 8) * DHD + wd + ni * 8 + cc;
            *(float2*)d0 = make_float2(acc[ni][0], acc[ni][1]);
            *(float2*)d1 = make_float2(acc[ni][2], acc[ni][3]);
        }
    }
    if (t < 64) {
        size_t sbi = (((size_t)b * HH + h) * NSPLIT + split) * NLAT + t;
        g_pm[sbi] = mf[t];
        g_pl[sbi] = lf[t];
    }
}

// ---- pass B: combine split partials -> attn output (b, q, h*64+d) ----
__global__ __launch_bounds__(64) void attn_combine_kernel() {
    int q = blockIdx.x, h = blockIdx.y, b = blockIdx.z;
    int d = threadIdx.x;
    size_t sb = (((size_t)b * HH + h) * NSPLIT) * NLAT + q;
    float mg = -1e30f;
    #pragma unroll
    for (int s = 0; s < NSPLIT; s++) mg = fmaxf(mg, g_pm[sb + (size_t)s * NLAT]);
    float denom = 0.f, a = 0.f;
    #pragma unroll
    for (int s = 0; s < NSPLIT; s++) {
        float w = __expf(g_pm[sb + (size_t)s * NLAT] - mg);
        denom += g_pl[sb + (size_t)s * NLAT] * w;
        a += g_pacc[((((size_t)b * HH + h) * NSPLIT + s) * NLAT + q) * DHD + d] * w;
    }
    g_attnout[((size_t)b * NLAT + q) * INNER + h * DHD + d] = a / denom;
}

extern "C" void kernel_launch(void* const* d_in, const int* in_sizes, int n_in,
                              void* d_out, int out_size) {
    const float* x    = (const float*)d_in[0];
    const float* lat  = (const float*)d_in[1];
    const void*  mask = d_in[2];
    const float* gate = (const float*)d_in[3];
    const float* gm   = (const float*)d_in[4];
    const float* bm   = (const float*)d_in[5];
    const float* gl   = (const float*)d_in[6];
    const float* bl   = (const float*)d_in[7];
    const float* Wq   = (const float*)d_in[8];
    const float* Wk   = (const float*)d_in[9];
    const float* Wv   = (const float*)d_in[10];
    const float* Wout = (const float*)d_in[11];
    float* out = (float*)d_out;

    cudaFuncSetAttribute(kv_mma_kernel,
                         cudaFuncAttributeMaxDynamicSharedMemorySize, GEMM_SMEM);
    cudaFuncSetAttribute(attn_mma_kernel,
                         cudaFuncAttributeMaxDynamicSharedMemorySize, ATT_SMEM);

    // Launch order puts kv_mma_kernel 4th (the slot ncu's -s/-c window captures).
    ln_lat_kernel<<<BB * NLAT, 256>>>(lat, gl, bl, (const unsigned int*)mask);
    prep_a_kernel<<<MROWS / 8, 256>>>(x, gm, bm, gate);
    prep_w_kernel<<<dim3(32, 32), 256>>>(Wk, Wv);
    kv_mma_kernel<<<dim3(8, 516), 256, GEMM_SMEM>>>();
    // Q = lat_ln @ Wq, scaled by DIM_HEAD^-0.5 = 0.125
    sgemm_kernel<<<dim3(INNER / 64, (BB * NLAT) / 64), 256>>>(
        Wq, nullptr, BB * NLAT, INNER, DD, DD, INNER, INNER, 0.125f, 0);
    attn_mma_kernel<<<dim3(NSPLIT, HH, BB), 256, ATT_SMEM>>>(mask);
    attn_combine_kernel<<<dim3(NLAT, HH, BB), 64>>>();
    sgemm_kernel<<<dim3(DD / 64, (BB * NLAT) / 64), 256>>>(
        Wout, out, BB * NLAT, DD, INNER, INNER, DD, DD, 1.0f, 1);
}

// round 14
// speedup vs baseline: 1.3966x; 1.0013x over previous
#include <cuda_runtime.h>
#include <cuda_bf16.h>
#include <cuda_fp16.h>
#include <cstdint>

// Problem dims (fixed by the dataset)
#define BB     8
#define FF     8192
#define NLAT   64
#define DD     1024
#define HH     8
#define DHD    64
#define INNER  512
#define KVLEN  (FF + NLAT)          // 8256
#define MROWS  (BB * KVLEN)         // 66048
#define NSPLIT 16
#define JT     64                    // kv tile in attention
#define NTILES (KVLEN / JT)          // 129
#define TPS    ((NTILES + NSPLIT - 1) / NSPLIT)  // 9
#define LN_EPS 1e-5f

// ---------------- family-safe PTX helpers (sm_80-era; no 'a'-features) ------
__device__ __forceinline__ uint32_t smem_u32(const void* p) {
    uint32_t a;
    asm("{ .reg .u64 t; cvta.to.shared.u64 t, %1; cvt.u32.u64 %0, t; }" : "=r"(a) : "l"(p));
    return a;
}
__device__ __forceinline__ void cp_async16(uint32_t dst, const void* src) {
    asm volatile("cp.async.cg.shared.global [%0], [%1], 16;" :: "r"(dst), "l"(src));
}
#define CP_COMMIT() asm volatile("cp.async.commit_group;" ::: "memory")
#define CP_WAIT(n)  asm volatile("cp.async.wait_group %0;" :: "n"(n) : "memory")

__device__ __forceinline__ void ldsm_x4(uint32_t* r, uint32_t addr) {
    asm volatile("ldmatrix.sync.aligned.m8n8.x4.shared.b16 {%0,%1,%2,%3}, [%4];"
        : "=r"(r[0]), "=r"(r[1]), "=r"(r[2]), "=r"(r[3]) : "r"(addr));
}
__device__ __forceinline__ void ldsm_x4_trans(uint32_t* r, uint32_t addr) {
    asm volatile("ldmatrix.sync.aligned.m8n8.x4.trans.shared.b16 {%0,%1,%2,%3}, [%4];"
        : "=r"(r[0]), "=r"(r[1]), "=r"(r[2]), "=r"(r[3]) : "r"(addr));
}
// fp16 mma
__device__ __forceinline__ void mma16816h(float* c, const uint32_t* a,
                                          uint32_t b0, uint32_t b1) {
    asm volatile(
        "mma.sync.aligned.m16n8k16.row.col.f32.f16.f16.f32 "
        "{%0,%1,%2,%3}, {%4,%5,%6,%7}, {%8,%9}, {%0,%1,%2,%3};"
        : "+f"(c[0]), "+f"(c[1]), "+f"(c[2]), "+f"(c[3])
        : "r"(a[0]), "r"(a[1]), "r"(a[2]), "r"(a[3]), "r"(b0), "r"(b1));
}

// -------- scratch (device globals; no allocations allowed) --------
__device__ float          g_lat_ln[BB * NLAT * DD];                       // 2 MB
__device__ __half         g_af[(size_t)MROWS * DD];                       // 135 MB (A fp16)
__device__ __half         g_bf[1024 * 1024];                              // 2 MB  [n][k] fp16
__device__ __half         g_kvf[(size_t)MROWS * 1024];                    // 135 MB (cols 0-511 K, 512-1023 V)
__device__ float          g_qmat[BB * NLAT * INNER];                      // 1 MB
__device__ float          g_attnout[BB * NLAT * INNER];                   // 1 MB
__device__ float          g_pacc[(size_t)BB * HH * NSPLIT * NLAT * DHD];  // 16.8 MB
__device__ float          g_pm[BB * HH * NSPLIT * NLAT];
__device__ float          g_pl[BB * HH * NSPLIT * NLAT];
__device__ int            g_mask_is_byte;

// ---- LayerNorm of latents + (block 0) mask dtype detection ----
__global__ __launch_bounds__(256) void ln_lat_kernel(const float* __restrict__ lat,
                                                     const float* __restrict__ gamma,
                                                     const float* __restrict__ beta,
                                                     const unsigned int* __restrict__ mask_w) {
    int row = blockIdx.x;
    int t = threadIdx.x;
    if (row == 0 && t == 0) {
        unsigned int acc = 0;
        #pragma unroll
        for (int i = 0; i < 64; i++) acc |= mask_w[i];
        g_mask_is_byte = (acc > 1u) ? 1 : 0;
    }
    float4 v = ((const float4*)(lat + (size_t)row * DD))[t];
    __shared__ float rs[256], rq[256];
    rs[t] = v.x + v.y + v.z + v.w;
    rq[t] = v.x*v.x + v.y*v.y + v.z*v.z + v.w*v.w;
    __syncthreads();
    for (int off = 128; off > 0; off >>= 1) {
        if (t < off) { rs[t] += rs[t + off]; rq[t] += rq[t + off]; }
        __syncthreads();
    }
    float mu   = rs[0] * (1.f / DD);
    float var  = rq[0] * (1.f / DD) - mu * mu;
    float rstd = rsqrtf(var + LN_EPS);
    float4 gv = ((const float4*)gamma)[t];
    float4 bv = ((const float4*)beta)[t];
    float4 o;
    o.x = (v.x - mu) * rstd * gv.x + bv.x;
    o.y = (v.y - mu) * rstd * gv.y + bv.y;
    o.z = (v.z - mu) * rstd * gv.z + bv.z;
    o.w = (v.w - mu) * rstd * gv.w + bv.w;
    ((float4*)(g_lat_ln + (size_t)row * DD))[t] = o;
}

// ---- fused LN + fp16 store of A: one row per warp, shuffle reduction ----
__global__ __launch_bounds__(256) void prep_a_kernel(const float* __restrict__ x,
                                                     const float* __restrict__ gm_,
                                                     const float* __restrict__ bm_,
                                                     const float* __restrict__ gate_p) {
    int wid = threadIdx.x >> 5, lane = threadIdx.x & 31;
    int row = blockIdx.x * 8 + wid;       // 0..MROWS-1 (grid = MROWS/8)
    int b = row / KVLEN;
    int r = row - b * KVLEN;
    float4 v[8];
    const float4* src;
    if (r < FF) src = (const float4*)(x + ((size_t)b * FF + r) * DD);
    else        src = (const float4*)(g_lat_ln + ((size_t)b * NLAT + (r - FF)) * DD);
    #pragma unroll
    for (int i = 0; i < 8; i++) v[i] = src[lane + 32 * i];

    if (r < FF) {
        float s = 0.f, q = 0.f;
        #pragma unroll
        for (int i = 0; i < 8; i++) {
            s += v[i].x + v[i].y + v[i].z + v[i].w;
            q += v[i].x*v[i].x + v[i].y*v[i].y + v[i].z*v[i].z + v[i].w*v[i].w;
        }
        #pragma unroll
        for (int off = 16; off > 0; off >>= 1) {
            s += __shfl_xor_sync(0xffffffffu, s, off);
            q += __shfl_xor_sync(0xffffffffu, q, off);
        }
        float mu   = s * (1.f / DD);
        float var  = q * (1.f / DD) - mu * mu;
        float rstd = rsqrtf(var + LN_EPS);
        #pragma unroll
        for (int i = 0; i < 8; i++) {
            float4 gv = ((const float4*)gm_)[lane + 32 * i];
            float4 bv = ((const float4*)bm_)[lane + 32 * i];
            v[i].x = (v[i].x - mu) * rstd * gv.x + bv.x;
            v[i].y = (v[i].y - mu) * rstd * gv.y + bv.y;
            v[i].z = (v[i].z - mu) * rstd * gv.z + bv.z;
            v[i].w = (v[i].w - mu) * rstd * gv.w + bv.w;
        }
    } else {
        float gate = gate_p[0];
        #pragma unroll
        for (int i = 0; i < 8; i++) {
            v[i].x *= gate; v[i].y *= gate; v[i].z *= gate; v[i].w *= gate;
        }
    }
    uint2* dst = (uint2*)(g_af + (size_t)row * DD);
    #pragma unroll
    for (int i = 0; i < 8; i++) {
        __half2 h01 = __floats2half2_rn(v[i].x, v[i].y);
        __half2 h23 = __floats2half2_rn(v[i].z, v[i].w);
        uint2 u;
        u.x = *(uint32_t*)&h01;
        u.y = *(uint32_t*)&h23;
        dst[lane + 32 * i] = u;
    }
}

// ---- transpose [Wk|Wv] (k-major [1024][512] each) into B[n][k] fp16 ----
__global__ __launch_bounds__(256) void prep_w_kernel(const float* __restrict__ Wk,
                                                     const float* __restrict__ Wv) {
    __shared__ float tile[32][33];
    int n0 = blockIdx.x * 32;           // 0..1023 (n of concat)
    int k0 = blockIdx.y * 32;
    int tx = threadIdx.x & 31, ty = threadIdx.x >> 5;  // 32 x 8
    const float* W = (n0 < 512) ? Wk : Wv;
    int nn0 = (n0 < 512) ? n0 : (n0 - 512);
    for (int i = ty; i < 32; i += 8)
        tile[i][tx] = W[(size_t)(k0 + i) * 512 + nn0 + tx];
    __syncthreads();
    for (int i = ty; i < 32; i += 8) {
        float v = tile[tx][i];          // = W[k0+tx][nn0+i]
        g_bf[(size_t)(n0 + i) * 1024 + k0 + tx] = __float2half_rn(v);
    }
}

// ---- HMMA (mma.sync fp16, 1-term) K/V projection: kv = A @ B^T ----
// R11-proven shape: BM=128, BN=128, BK=32, 8 warps (4m x 2n), 32x64 warp tile,
// 2 CTAs/SM. This round: NSTAGE 4->5 (prefetch distance 4; 200 KB @ 2 CTAs).
#define AS_STRIDE_H 40                      // halves per SMEM row
#define MAT_BYTES   (128 * AS_STRIDE_H * 2) // 10240 per matrix tile
#define STG_BYTES   (2 * MAT_BYTES)         // 20480 per stage (A, B)
#define NSTAGE      5
#define GEMM_SMEM   (NSTAGE * STG_BYTES)    // 102400
#define NCHUNK      32

__global__ __launch_bounds__(256, 2) void kv_mma_kernel() {
    extern __shared__ char smem[];
    const uint32_t sbase = smem_u32(smem);
    const int t = threadIdx.x;
    const int wid = t >> 5, lane = t & 31;
    const int ntile = blockIdx.x;            // 0..7
    const int mtile = blockIdx.y;            // 0..515
    const size_t arow0 = (size_t)mtile * 128;
    const int    brow0 = ntile * 128;

    // global load assignment: row r_ld, two consecutive 16B segs
    const int r_ld = t >> 1;
    const int seg0 = (t & 1) * 2;            // 0 or 2 (of 4 segs/row)
    const __half* gA = g_af + (arow0 + r_ld) * 1024 + seg0 * 8;
    const __half* gB = g_bf + (size_t)(brow0 + r_ld) * 1024 + seg0 * 8;
    const uint32_t sAdst = sbase + r_ld * 80 + seg0 * 16;

    #define LOAD_CHUNK(chunk, stg_) do {                                       \
        uint32_t sb_ = sAdst + (stg_) * STG_BYTES;                             \
        int ko_ = (chunk) * 32;                                                \
        cp_async16(sb_,                  gA + ko_);                            \
        cp_async16(sb_ + 16,             gA + ko_ + 8);                        \
        cp_async16(sb_ + MAT_BYTES,      gB + ko_);                            \
        cp_async16(sb_ + MAT_BYTES + 16, gB + ko_ + 8);                        \
    } while (0)

    // warp tile: wm in {0,32,64,96}, wn in {0,64}
    const int wm = (wid & 3) * 32;
    const int wn = (wid >> 2) * 64;

    const int a_off_h = (wm + (lane & 15)) * AS_STRIDE_H + (lane >> 4) * 8;
    const int b_off_h = (wn + (lane & 7) + ((lane >> 3) & 1) * 8) * AS_STRIDE_H
                        + (lane >> 4) * 8;

    float acc[2][8][4];
    #pragma unroll
    for (int i = 0; i < 2; i++)
        #pragma unroll
        for (int j = 0; j < 8; j++)
            #pragma unroll
            for (int c = 0; c < 4; c++) acc[i][j][c] = 0.f;

    LOAD_CHUNK(0, 0); CP_COMMIT();
    LOAD_CHUNK(1, 1); CP_COMMIT();
    LOAD_CHUNK(2, 2); CP_COMMIT();
    LOAD_CHUNK(3, 3); CP_COMMIT();

    int st = 0;  // stage of current chunk
    for (int chunk = 0; chunk < NCHUNK; chunk++) {
        // committed = 4 + min(chunk, NCHUNK-4); need group 'chunk' done
        if (chunk < NCHUNK - 3)       { CP_WAIT(3); }
        else if (chunk == NCHUNK - 3) { CP_WAIT(2); }
        else if (chunk == NCHUNK - 2) { CP_WAIT(1); }
        else                          { CP_WAIT(0); }
        __syncthreads();   // also protects WAR on the stage being refilled
        if (chunk + 4 < NCHUNK) {
            int stn = st + 4; if (stn >= NSTAGE) stn -= NSTAGE;
            LOAD_CHUNK(chunk + 4, stn);
            CP_COMMIT();
        }

        const uint32_t stg = sbase + st * STG_BYTES;
        #pragma unroll
        for (int ks = 0; ks < 2; ks++) {
            uint32_t a[2][4];
            #pragma unroll
            for (int mi = 0; mi < 2; mi++) {
                uint32_t ao = stg + (a_off_h + mi * 16 * AS_STRIDE_H + ks * 16) * 2;
                ldsm_x4(a[mi], ao);
            }
            #pragma unroll
            for (int nip = 0; nip < 4; nip++) {
                uint32_t bb[4];
                uint32_t bo = stg + MAT_BYTES
                            + (b_off_h + nip * 16 * AS_STRIDE_H + ks * 16) * 2;
                ldsm_x4(bb, bo);
                #pragma unroll
                for (int mi = 0; mi < 2; mi++) {
                    mma16816h(acc[mi][nip * 2],     a[mi], bb[0], bb[2]);
                    mma16816h(acc[mi][nip * 2 + 1], a[mi], bb[1], bb[3]);
                }
            }
        }
        if (++st == NSTAGE) st = 0;
    }

    // epilogue: write kv as single fp16
    const int col0 = ntile * 128 + wn + (lane & 3) * 2;
    #pragma unroll
    for (int mi = 0; mi < 2; mi++) {
        size_t row = arow0 + wm + mi * 16 + (lane >> 2);
        #pragma unroll
        for (int ni = 0; ni < 8; ni++) {
            size_t o0 = row * 1024 + col0 + ni * 8;
            size_t o1 = (row + 8) * 1024 + col0 + ni * 8;
            *(__half2*)(g_kvf + o0) = __floats2half2_rn(acc[mi][ni][0], acc[mi][ni][1]);
            *(__half2*)(g_kvf + o1) = __floats2half2_rn(acc[mi][ni][2], acc[mi][ni][3]);
        }
    }
}

// ---- generic small sgemm (mode 0: Q proj, mode 1: out proj) ----
__global__ __launch_bounds__(256) void sgemm_kernel(const float* __restrict__ Bmat,
                                                    float* __restrict__ Cext,
                                                    int M, int N, int K,
                                                    int lda, int ldb, int ldc,
                                                    float alpha, int mode) {
    const float* A = (mode == 0) ? g_lat_ln : g_attnout;
    float* C = (mode == 0) ? g_qmat : Cext;
    __shared__ float As[16][65];
    __shared__ float Bs[16][65];
    int t = threadIdx.x;
    int tx = t & 15, ty = t >> 4;
    int n0 = blockIdx.x * 64;
    int m0 = blockIdx.y * 64;
    float acc[4][4] = {};
    for (int k0 = 0; k0 < K; k0 += 16) {
        #pragma unroll
        for (int l = 0; l < 4; l++) {
            int idx = t + l * 256;
            int row = idx >> 4, kk = idx & 15;
            As[kk][row] = A[(size_t)(m0 + row) * lda + k0 + kk];
        }
        #pragma unroll
        for (int l = 0; l < 4; l++) {
            int idx = t + l * 256;
            int kk = idx >> 6, col = idx & 63;
            Bs[kk][col] = Bmat[(size_t)(k0 + kk) * ldb + n0 + col];
        }
        __syncthreads();
        #pragma unroll
        for (int kk = 0; kk < 16; kk++) {
            float a[4], bb[4];
            #pragma unroll
            for (int i = 0; i < 4; i++) a[i]  = As[kk][ty * 4 + i];
            #pragma unroll
            for (int j = 0; j < 4; j++) bb[j] = Bs[kk][tx * 4 + j];
            #pragma unroll
            for (int i = 0; i < 4; i++)
                #pragma unroll
                for (int j = 0; j < 4; j++)
                    acc[i][j] = fmaf(a[i], bb[j], acc[i][j]);
        }
        __syncthreads();
    }
    #pragma unroll
    for (int i = 0; i < 4; i++)
        #pragma unroll
        for (int j = 0; j < 4; j++)
            C[(size_t)(m0 + ty * 4 + i) * ldc + n0 + tx * 4 + j] = alpha * acc[i][j];
}

// ---- split-KV flash attention, fp16 HMMA, JT=64 ----
// Q split fp16 hi/lo (exact to 2^-22); K,V single fp16; P split fp16 hi/lo.
// JT=64 halves tile count (9 vs 17) -> half the barrier/serial-phase overhead.
#define ATT_QSTR 72
#define ATT_KSTR 72
#define ATT_PSTR 72
#define ATT_SSTR 72
#define AOFF_QH 0
#define AOFF_QL 9216
#define AOFF_K  18432
#define AOFF_V  27648
#define AOFF_SP 36864
#define AOFF_PH 55296
#define AOFF_PL 64512
#define AOFF_M  73728
#define AOFF_L  73984
#define AOFF_AL 74240
#define AOFF_MN 74496
#define AOFF_VD 74752
#define ATT_SMEM 75008

__global__ __launch_bounds__(256) void attn_mma_kernel(const void* __restrict__ mask_raw) {
    extern __shared__ char sm[];
    const uint32_t sb = smem_u32(sm);
    const int split = blockIdx.x, h = blockIdx.y, b = blockIdx.z;
    const int t = threadIdx.x, wid = t >> 5, lane = t & 31;
    const unsigned char* mask8 = (const unsigned char*)mask_raw;
    const int*           mask32 = (const int*)mask_raw;
    const int is_byte = g_mask_is_byte;

    float* mf  = (float*)(sm + AOFF_M);
    float* lf  = (float*)(sm + AOFF_L);
    float* alf = (float*)(sm + AOFF_AL);
    float* mnf = (float*)(sm + AOFF_MN);
    float* vdf = (float*)(sm + AOFF_VD);

    // prologue: load+split Q slice (64q x 64d) to Qh/Ql (fp16 hi/lo)
    {
        int q = t >> 2, dg = (t & 3) * 16;
        const float4* src = (const float4*)(g_qmat + ((size_t)(b * NLAT + q)) * INNER
                                            + h * DHD + dg);
        __half2* qh = (__half2*)(sm + AOFF_QH + (q * ATT_QSTR + dg) * 2);
        __half2* ql = (__half2*)(sm + AOFF_QL + (q * ATT_QSTR + dg) * 2);
        #pragma unroll
        for (int i = 0; i < 4; i++) {
            float4 v = src[i];
            __half2 h01 = __floats2half2_rn(v.x, v.y);
            __half2 h23 = __floats2half2_rn(v.z, v.w);
            __half2 l01 = __floats2half2_rn(v.x - __half2float(__low2half(h01)),
                                            v.y - __half2float(__high2half(h01)));
            __half2 l23 = __floats2half2_rn(v.z - __half2float(__low2half(h23)),
                                            v.w - __half2float(__high2half(h23)));
            qh[i * 2] = h01; qh[i * 2 + 1] = h23;
            ql[i * 2] = l01; ql[i * 2 + 1] = l23;
        }
    }
    if (t < 64) { mf[t] = -1e30f; lf[t] = 0.f; }

    float acc[4][4];
    #pragma unroll
    for (int i = 0; i < 4; i++)
        #pragma unroll
        for (int j = 0; j < 4; j++) acc[i][j] = 0.f;

    const int t0 = split * TPS;
    int tcnt = NTILES - t0;
    if (tcnt > TPS) tcnt = TPS;
    if (tcnt < 0) tcnt = 0;
    __syncthreads();

    for (int it = 0; it < tcnt; it++) {
        const int j0 = (t0 + it) * JT;
        // phase 1: K/V fp16 tiles (64 rows x 64 cols each), 2 segs/thread/array
        {
            int seg = (t & 7) * 8;         // halves
            #pragma unroll
            for (int it2 = 0; it2 < 2; it2++) {
                int row = (t >> 3) + it2 * 32;
                const __half* src = g_kvf + ((size_t)b * KVLEN + j0 + row) * 1024;
                uint32_t doff = (uint32_t)(row * ATT_KSTR + seg) * 2;
                *(uint4*)(sm + AOFF_K + doff) = *(const uint4*)(src + h * DHD + seg);
                *(uint4*)(sm + AOFF_V + doff) = *(const uint4*)(src + 512 + h * DHD + seg);
            }
        }
        if (t < JT) {
            int row = j0 + t;
            bool valid;
            if (row >= FF) valid = true;
            else {
                int mv = is_byte ? (int)mask8[b * FF + row] : mask32[b * FF + row];
                valid = (mv == 0);
            }
            vdf[t] = valid ? 1.f : 0.f;
        }
        __syncthreads();

        // phase 2: S = Q K^T (2-term fp16), warp tile 16q x 32j, write SP[q][j]
        {
            const int wq = (wid & 3) * 16, wj = (wid >> 2) * 32;
            float c[4][4];
            #pragma unroll
            for (int jb = 0; jb < 4; jb++)
                #pragma unroll
                for (int cc2 = 0; cc2 < 4; cc2++) c[jb][cc2] = 0.f;
            #pragma unroll
            for (int ks = 0; ks < 4; ks++) {
                uint32_t aqh[4], aql[4], bk0[4], bk1[4];
                uint32_t aoff = ((wq + (lane & 15)) * ATT_QSTR + ks * 16
                                 + (lane >> 4) * 8) * 2;
                ldsm_x4(aqh, sb + AOFF_QH + aoff);
                ldsm_x4(aql, sb + AOFF_QL + aoff);
                uint32_t brow = (lane & 7) + ((lane >> 3) & 1) * 8;
                uint32_t bo0 = ((wj + brow) * ATT_KSTR + ks * 16 + (lane >> 4) * 8) * 2;
                uint32_t bo1 = ((wj + 16 + brow) * ATT_KSTR + ks * 16 + (lane >> 4) * 8) * 2;
                ldsm_x4(bk0, sb + AOFF_K + bo0);
                ldsm_x4(bk1, sb + AOFF_K + bo1);
                mma16816h(c[0], aqh, bk0[0], bk0[2]);
                mma16816h(c[0], aql, bk0[0], bk0[2]);
                mma16816h(c[1], aqh, bk0[1], bk0[3]);
                mma16816h(c[1], aql, bk0[1], bk0[3]);
                mma16816h(c[2], aqh, bk1[0], bk1[2]);
                mma16816h(c[2], aql, bk1[0], bk1[2]);
                mma16816h(c[3], aqh, bk1[1], bk1[3]);
                mma16816h(c[3], aql, bk1[1], bk1[3]);
            }
            float* sp = (float*)(sm + AOFF_SP);
            int r = lane >> 2, cc = (lane & 3) * 2;
            #pragma unroll
            for (int jb = 0; jb < 4; jb++) {
                *(float2*)&sp[(wq + r) * ATT_SSTR + wj + jb * 8 + cc] =
                    make_float2(c[jb][0], c[jb][1]);
                *(float2*)&sp[(wq + r + 8) * ATT_SSTR + wj + jb * 8 + cc] =
                    make_float2(c[jb][2], c[jb][3]);
            }
        }
        __syncthreads();

        // phase 3: masked row max -> mnew, alpha
        if (t < 64) {
            const float* sp = (const float*)(sm + AOFF_SP) + t * ATT_SSTR;
            float mx = -1e30f;
            #pragma unroll
            for (int j = 0; j < JT; j++)
                mx = fmaxf(mx, (vdf[j] != 0.f) ? sp[j] : -1e30f);
            float mold = mf[t];
            float mnew = fmaxf(mold, mx);
            mnf[t] = mnew;
            alf[t] = __expf(mold - mnew);
            mf[t]  = mnew;
        }
        __syncthreads();

        // phase 4: P = exp(S - mnew) masked; split to Ph/Pl (fp16); acc *= alpha
        {
            int q = t >> 2, jg = (t & 3) * 16;
            float* sp = (float*)(sm + AOFF_SP) + q * ATT_SSTR + jg;
            float mn = mnf[q];
            __half2* ph = (__half2*)(sm + AOFF_PH + (q * ATT_PSTR + jg) * 2);
            __half2* pl = (__half2*)(sm + AOFF_PL + (q * ATT_PSTR + jg) * 2);
            #pragma unroll
            for (int i = 0; i < 16; i += 2) {
                float e0 = (vdf[jg + i]     != 0.f) ? __expf(sp[i]     - mn) : 0.f;
                float e1 = (vdf[jg + i + 1] != 0.f) ? __expf(sp[i + 1] - mn) : 0.f;
                sp[i] = e0; sp[i + 1] = e1;
                __half2 hh = __floats2half2_rn(e0, e1);
                __half2 ll = __floats2half2_rn(e0 - __half2float(__low2half(hh)),
                                               e1 - __half2float(__high2half(hh)));
                ph[i >> 1] = hh; pl[i >> 1] = ll;
            }
            const int wq = (wid & 3) * 16;
            float a1 = alf[wq + (lane >> 2)];
            float a2 = alf[wq + (lane >> 2) + 8];
            #pragma unroll
            for (int ni = 0; ni < 4; ni++) {
                acc[ni][0] *= a1; acc[ni][1] *= a1;
                acc[ni][2] *= a2; acc[ni][3] *= a2;
            }
        }
        __syncthreads();

        // phase 5: l update + O += P V (2-term fp16, K-dim 64)
        if (t < 64) {
            const float* sp = (const float*)(sm + AOFF_SP) + t * ATT_SSTR;
            float s = 0.f;
            #pragma unroll
            for (int j = 0; j < JT; j++) s += sp[j];
            lf[t] = lf[t] * alf[t] + s;
        }
        {
            const int wq = (wid & 3) * 16, wd = (wid >> 2) * 32;
            #pragma unroll
            for (int ks = 0; ks < 4; ks++) {
                uint32_t aph[4], apl[4], bv0[4], bv1[4];
                uint32_t aoff = ((wq + (lane & 15)) * ATT_PSTR + ks * 16
                                 + (lane >> 4) * 8) * 2;
                ldsm_x4(aph, sb + AOFF_PH + aoff);
                ldsm_x4(apl, sb + AOFF_PL + aoff);
                uint32_t vrow = ks * 16 + (lane & 15);
                uint32_t v0 = (vrow * ATT_KSTR + wd + (lane >> 4) * 8) * 2;
                uint32_t v1 = (vrow * ATT_KSTR + wd + 16 + (lane >> 4) * 8) * 2;
                ldsm_x4_trans(bv0, sb + AOFF_V + v0);
                ldsm_x4_trans(bv1, sb + AOFF_V + v1);
                mma16816h(acc[0], aph, bv0[0], bv0[1]);
                mma16816h(acc[0], apl, bv0[0], bv0[1]);
                mma16816h(acc[1], aph, bv0[2], bv0[3]);
                mma16816h(acc[1], apl, bv0[2], bv0[3]);
                mma16816h(acc[2], aph, bv1[0], bv1[1]);
                mma16816h(acc[2], apl, bv1[0], bv1[1]);
                mma16816h(acc[3], aph, bv1[2], bv1[3]);
                mma16816h(acc[3], apl, bv1[2], bv1[3]);
            }
        }
        __syncthreads();
    }

    // epilogue: write partials
    {
        const int wq = (wid & 3) * 16, wd = (wid >> 2) * 32;
        size_t pbase = ((((size_t)b * HH + h) * NSPLIT + split) * NLAT) * (size_t)DHD;
        int r = lane >> 2, cc = (lane & 3) * 2;
        #pragma unroll
        for (int ni = 0; ni < 4; ni++) {
            float* d0 = g_pacc + pbase + (size_t)(wq + r) * DHD + wd + ni * 8 + cc;
            float* d1 = g_pacc + pbase + (size_t)(wq + r + 8) * DHD + wd + ni * 8 + cc;
            *(float2*)d0 = make_float2(acc[ni][0], acc[ni][1]);
            *(float2*)d1 = make_float2(acc[ni][2], acc[ni][3]);
        }
    }
    if (t < 64) {
        size_t sbi = (((size_t)b * HH + h) * NSPLIT + split) * NLAT + t;
        g_pm[sbi] = mf[t];
        g_pl[sbi] = lf[t];
    }
}

// ---- pass B: combine split partials -> attn output (b, q, h*64+d) ----
__global__ __launch_bounds__(64) void attn_combine_kernel() {
    int q = blockIdx.x, h = blockIdx.y, b = blockIdx.z;
    int d = threadIdx.x;
    size_t sb = (((size_t)b * HH + h) * NSPLIT) * NLAT + q;
    float mg = -1e30f;
    #pragma unroll
    for (int s = 0; s < NSPLIT; s++) mg = fmaxf(mg, g_pm[sb + (size_t)s * NLAT]);
    float denom = 0.f, a = 0.f;
    #pragma unroll
    for (int s = 0; s < NSPLIT; s++) {
        float w = __expf(g_pm[sb + (size_t)s * NLAT] - mg);
        denom += g_pl[sb + (size_t)s * NLAT] * w;
        a += g_pacc[((((size_t)b * HH + h) * NSPLIT + s) * NLAT + q) * DHD + d] * w;
    }
    g_attnout[((size_t)b * NLAT + q) * INNER + h * DHD + d] = a / denom;
}

extern "C" void kernel_launch(void* const* d_in, const int* in_sizes, int n_in,
                              void* d_out, int out_size) {
    const float* x    = (const float*)d_in[0];
    const float* lat  = (const float*)d_in[1];
    const void*  mask = d_in[2];
    const float* gate = (const float*)d_in[3];
    const float* gm   = (const float*)d_in[4];
    const float* bm   = (const float*)d_in[5];
    const float* gl   = (const float*)d_in[6];
    const float* bl   = (const float*)d_in[7];
    const float* Wq   = (const float*)d_in[8];
    const float* Wk   = (const float*)d_in[9];
    const float* Wv   = (const float*)d_in[10];
    const float* Wout = (const float*)d_in[11];
    float* out = (float*)d_out;

    cudaFuncSetAttribute(kv_mma_kernel,
                         cudaFuncAttributeMaxDynamicSharedMemorySize, GEMM_SMEM);
    cudaFuncSetAttribute(attn_mma_kernel,
                         cudaFuncAttributeMaxDynamicSharedMemorySize, ATT_SMEM);

    // Launch order puts kv_mma_kernel 4th (the slot ncu's -s/-c window captures).
    ln_lat_kernel<<<BB * NLAT, 256>>>(lat, gl, bl, (const unsigned int*)mask);
    prep_a_kernel<<<MROWS / 8, 256>>>(x, gm, bm, gate);
    prep_w_kernel<<<dim3(32, 32), 256>>>(Wk, Wv);
    kv_mma_kernel<<<dim3(8, 516), 256, GEMM_SMEM>>>();
    // Q = lat_ln @ Wq, scaled by DIM_HEAD^-0.5 = 0.125
    sgemm_kernel<<<dim3(INNER / 64, (BB * NLAT) / 64), 256>>>(
        Wq, nullptr, BB * NLAT, INNER, DD, DD, INNER, INNER, 0.125f, 0);
    attn_mma_kernel<<<dim3(NSPLIT, HH, BB), 256, ATT_SMEM>>>(mask);
    attn_combine_kernel<<<dim3(NLAT, HH, BB), 64>>>();
    sgemm_kernel<<<dim3(DD / 64, (BB * NLAT) / 64), 256>>>(
        Wout, out, BB * NLAT, DD, INNER, INNER, DD, DD, 1.0f, 1);
}